// round 1
// baseline (speedup 1.0000x reference)
#include <cuda_runtime.h>
#include <math.h>

#define N_NODES 50000
#define N_EDGES 600000
#define D 128
#define REL_DIM 100
#define N_REL 40

// ---------------- device scratch (no allocations allowed) ----------------
__device__ float g_h[(size_t)N_NODES * D];   // X @ W
__device__ float g_s1[N_NODES];              // h . a[:D]
__device__ float g_s2[N_NODES];              // h . a[D:2D]
__device__ int   g_max[N_NODES];             // ordered-int encoded per-dst max logit
__device__ float g_sum[N_NODES];             // per-dst softmax denominator
__device__ float g_logit[N_EDGES];           // logit, then exp(logit - max)
__device__ float g_t[N_REL];                 // per-relation logit contribution

// ordered-int encoding for float atomicMax (monotone for all finite + inf)
__device__ __forceinline__ int enc_f(float f) {
    int i = __float_as_int(f);
    return i >= 0 ? i : (i ^ 0x7FFFFFFF);
}
__device__ __forceinline__ float dec_f(int k) {
    return __int_as_float(k >= 0 ? k : (k ^ 0x7FFFFFFF));
}

// ---------------- K0: init max/sum + compute per-relation term t ----------------
__global__ void k_init(const float* __restrict__ W_r, const float* __restrict__ a,
                       const float* __restrict__ rel_emb) {
    int i = blockIdx.x * blockDim.x + threadIdx.x;
    if (i < N_NODES) {
        g_max[i] = (int)0x807FFFFFu;  // enc(-inf)
        g_sum[i] = 0.0f;
    }
    if (blockIdx.x == 0) {
        __shared__ float v[REL_DIM];
        int t = threadIdx.x;
        if (t < REL_DIM) {
            float s = 0.0f;
            #pragma unroll 4
            for (int k = 0; k < D; k++) s = fmaf(W_r[t * D + k], a[2 * D + k], s);
            v[t] = s;
        }
        __syncthreads();
        if (t < N_REL) {
            float s = 0.0f;
            for (int j = 0; j < REL_DIM; j++) s = fmaf(rel_emb[t * REL_DIM + j], v[j], s);
            g_t[t] = s;
        }
    }
}

// ---------------- K1: fused SGEMM  h = X@W ; base = X@W_res + b_res -> out ----------------
// 64x64 tile, K split into 2 chunks of 64.  Block = 256 threads, 4x4 micro-tile.
#define AS_STRIDE 68
__global__ __launch_bounds__(256) void k_gemm(const float* __restrict__ X,
                                              const float* __restrict__ W,
                                              const float* __restrict__ Wres,
                                              const float* __restrict__ b_res,
                                              float* __restrict__ out) {
    __shared__ float As[64 * AS_STRIDE];   // [k][m] transposed
    __shared__ float Bs[64 * 64];          // [k][n]

    int tid = threadIdx.x;
    int tx = tid & 15;        // col group
    int ty = tid >> 4;        // row group
    int bm = blockIdx.x * 64;
    int bn = blockIdx.y * 64; // 0..255 in steps of 64
    const float* Bsrc = (bn < D) ? (W + bn) : (Wres + (bn - D));

    float acc[4][4] = {};

    for (int k0 = 0; k0 < D; k0 += 64) {
        // load A chunk: 64 rows x 64 k, transposed into As[k][m]
        {
            int m  = tid & 63;
            int kb = (tid >> 6) * 16;
            int gm = bm + m;
            #pragma unroll
            for (int i = 0; i < 4; i++) {
                float4 v = make_float4(0.f, 0.f, 0.f, 0.f);
                if (gm < N_NODES)
                    v = *(const float4*)(X + (size_t)gm * D + k0 + kb + i * 4);
                As[(kb + i * 4 + 0) * AS_STRIDE + m] = v.x;
                As[(kb + i * 4 + 1) * AS_STRIDE + m] = v.y;
                As[(kb + i * 4 + 2) * AS_STRIDE + m] = v.z;
                As[(kb + i * 4 + 3) * AS_STRIDE + m] = v.w;
            }
        }
        // load B chunk: 64 k x 64 n
        {
            int kr = tid >> 4;        // 0..15
            int n4 = (tid & 15) * 4;
            #pragma unroll
            for (int i = 0; i < 4; i++) {
                int k = kr + i * 16;
                float4 v = *(const float4*)(Bsrc + (size_t)(k0 + k) * D + n4);
                *(float4*)&Bs[k * 64 + n4] = v;
            }
        }
        __syncthreads();
        #pragma unroll
        for (int k = 0; k < 64; k++) {
            float4 av = *(const float4*)&As[k * AS_STRIDE + ty * 4];
            float4 bv = *(const float4*)&Bs[k * 64 + tx * 4];
            float ar[4] = {av.x, av.y, av.z, av.w};
            float br[4] = {bv.x, bv.y, bv.z, bv.w};
            #pragma unroll
            for (int i = 0; i < 4; i++)
                #pragma unroll
                for (int j = 0; j < 4; j++)
                    acc[i][j] = fmaf(ar[i], br[j], acc[i][j]);
        }
        __syncthreads();
    }

    #pragma unroll
    for (int i = 0; i < 4; i++) {
        int m = bm + ty * 4 + i;
        if (m >= N_NODES) continue;
        #pragma unroll
        for (int j = 0; j < 4; j++) {
            int n = bn + tx * 4 + j;
            float v = acc[i][j];
            if (n < D) g_h[(size_t)m * D + n] = v;
            else       out[(size_t)m * D + (n - D)] = v + b_res[n - D];
        }
    }
}

// ---------------- K2: per-node scalars s1 = h.a1, s2 = h.a2 (warp per node) ----------------
__global__ void k_dots(const float* __restrict__ a) {
    int gw = (blockIdx.x * blockDim.x + threadIdx.x) >> 5;
    int lane = threadIdx.x & 31;
    if (gw >= N_NODES) return;
    float4 h4 = *(const float4*)&g_h[(size_t)gw * D + lane * 4];
    float4 a1 = *(const float4*)(a + lane * 4);
    float4 a2 = *(const float4*)(a + D + lane * 4);
    float s1 = h4.x * a1.x + h4.y * a1.y + h4.z * a1.z + h4.w * a1.w;
    float s2 = h4.x * a2.x + h4.y * a2.y + h4.z * a2.z + h4.w * a2.w;
    #pragma unroll
    for (int o = 16; o > 0; o >>= 1) {
        s1 += __shfl_xor_sync(0xFFFFFFFFu, s1, o);
        s2 += __shfl_xor_sync(0xFFFFFFFFu, s2, o);
    }
    if (lane == 0) { g_s1[gw] = s1; g_s2[gw] = s2; }
}

// ---------------- K3: per-edge logit + atomic max per dst ----------------
__global__ void k_logit(const int* __restrict__ ei, const int* __restrict__ et) {
    int e = blockIdx.x * blockDim.x + threadIdx.x;
    if (e >= N_EDGES) return;
    int s = ei[e];
    int dd = ei[N_EDGES + e];
    float l = g_s1[dd] + g_s2[s] + g_t[et[e]];
    l = l > 0.0f ? l : 0.2f * l;   // leaky relu
    g_logit[e] = l;
    atomicMax(&g_max[dd], enc_f(l));
}

// ---------------- K4: exp(l - max) + atomic sum per dst ----------------
__global__ void k_expsum(const int* __restrict__ ei) {
    int e = blockIdx.x * blockDim.x + threadIdx.x;
    if (e >= N_EDGES) return;
    int dd = ei[N_EDGES + e];
    float m = dec_f(g_max[dd]);
    float ev = expf(g_logit[e] - m);
    g_logit[e] = ev;
    atomicAdd(&g_sum[dd], ev);
}

// ---------------- K5: scatter agg: out[dst] += alpha * h[src]  (warp per edge) ----------------
__global__ __launch_bounds__(256) void k_scatter(const int* __restrict__ ei,
                                                 float* __restrict__ out) {
    int e = blockIdx.x * 8 + (threadIdx.x >> 5);
    if (e >= N_EDGES) return;
    int lane = threadIdx.x & 31;
    int s = ei[e];
    int dd = ei[N_EDGES + e];
    float alpha = g_logit[e] / (g_sum[dd] + 1e-16f);
    float4 hv = *(const float4*)&g_h[(size_t)s * D + lane * 4];
    float* o = out + (size_t)dd * D + lane * 4;
    atomicAdd(o + 0, hv.x * alpha);
    atomicAdd(o + 1, hv.y * alpha);
    atomicAdd(o + 2, hv.z * alpha);
    atomicAdd(o + 3, hv.w * alpha);
}

// ---------------- K6: SELU in place ----------------
__global__ void k_selu(float* __restrict__ out) {
    int i = blockIdx.x * blockDim.x + threadIdx.x;
    if (i >= N_NODES * D) return;
    const float scale = 1.0507009873554805f;
    const float salpha = 1.7580993408473766f;  // scale * alpha
    float x = out[i];
    out[i] = x > 0.0f ? scale * x : salpha * expm1f(x);
}

// ---------------- launch ----------------
extern "C" void kernel_launch(void* const* d_in, const int* in_sizes, int n_in,
                              void* d_out, int out_size) {
    const float* X      = (const float*)d_in[0];
    const int*   ei     = (const int*)  d_in[1];  // [2, E]
    const int*   et     = (const int*)  d_in[2];  // [E]
    const float* W      = (const float*)d_in[3];
    const float* W_r    = (const float*)d_in[4];
    const float* a      = (const float*)d_in[5];
    const float* W_res  = (const float*)d_in[6];
    const float* b_res  = (const float*)d_in[7];
    const float* rel    = (const float*)d_in[8];
    float* out = (float*)d_out;

    k_init<<<(N_NODES + 255) / 256, 256>>>(W_r, a, rel);

    dim3 ggrid((N_NODES + 63) / 64, (2 * D) / 64);
    k_gemm<<<ggrid, 256>>>(X, W, W_res, b_res, out);

    k_dots<<<(N_NODES * 32 + 255) / 256, 256>>>(a);

    k_logit<<<(N_EDGES + 255) / 256, 256>>>(ei, et);
    k_expsum<<<(N_EDGES + 255) / 256, 256>>>(ei);
    k_scatter<<<(N_EDGES + 7) / 8, 256>>>(ei, out);

    k_selu<<<(N_NODES * D + 255) / 256, 256>>>(out);
}

// round 2
// speedup vs baseline: 1.2372x; 1.2372x over previous
#include <cuda_runtime.h>
#include <math.h>

#define N_NODES 50000
#define N_EDGES 600000
#define D 128
#define REL_DIM 100
#define N_REL 40

// ---------------- device scratch (no allocations allowed) ----------------
__device__ float g_h[(size_t)N_NODES * D];   // X @ W
__device__ float g_s1[N_NODES];              // h . a[:D]
__device__ float g_s2[N_NODES];              // h . a[D:2D]
__device__ float g_t[N_REL];                 // per-relation logit contribution
__device__ int   g_cnt[N_NODES];             // edges per dst
__device__ int   g_off[N_NODES];             // CSR start per dst
__device__ int   g_cur[N_NODES];             // fill cursor
__device__ int   g_esrc[N_EDGES];            // dst-sorted: source node per edge
__device__ float g_elog[N_EDGES];            // dst-sorted: leakyrelu logit per edge

// ---------------- K0: zero counts + compute per-relation term t ----------------
__global__ void k_init(const float* __restrict__ W_r, const float* __restrict__ a,
                       const float* __restrict__ rel_emb) {
    int i = blockIdx.x * blockDim.x + threadIdx.x;
    if (i < N_NODES) g_cnt[i] = 0;
    if (blockIdx.x == 0) {
        __shared__ float v[REL_DIM];
        int t = threadIdx.x;
        if (t < REL_DIM) {
            float s = 0.0f;
            #pragma unroll 4
            for (int k = 0; k < D; k++) s = fmaf(W_r[t * D + k], a[2 * D + k], s);
            v[t] = s;
        }
        __syncthreads();
        if (t < N_REL) {
            float s = 0.0f;
            for (int j = 0; j < REL_DIM; j++) s = fmaf(rel_emb[t * REL_DIM + j], v[j], s);
            g_t[t] = s;
        }
    }
}

// ---------------- K1: fused SGEMM  h = X@W ; base = X@W_res + b_res -> out ----------------
#define AS_STRIDE 68
__global__ __launch_bounds__(256) void k_gemm(const float* __restrict__ X,
                                              const float* __restrict__ W,
                                              const float* __restrict__ Wres,
                                              const float* __restrict__ b_res,
                                              float* __restrict__ out) {
    __shared__ float As[64 * AS_STRIDE];   // [k][m] transposed
    __shared__ float Bs[64 * 64];          // [k][n]

    int tid = threadIdx.x;
    int tx = tid & 15;
    int ty = tid >> 4;
    int bm = blockIdx.x * 64;
    int bn = blockIdx.y * 64;
    const float* Bsrc = (bn < D) ? (W + bn) : (Wres + (bn - D));

    float acc[4][4] = {};

    for (int k0 = 0; k0 < D; k0 += 64) {
        {
            int m  = tid & 63;
            int kb = (tid >> 6) * 16;
            int gm = bm + m;
            #pragma unroll
            for (int i = 0; i < 4; i++) {
                float4 v = make_float4(0.f, 0.f, 0.f, 0.f);
                if (gm < N_NODES)
                    v = *(const float4*)(X + (size_t)gm * D + k0 + kb + i * 4);
                As[(kb + i * 4 + 0) * AS_STRIDE + m] = v.x;
                As[(kb + i * 4 + 1) * AS_STRIDE + m] = v.y;
                As[(kb + i * 4 + 2) * AS_STRIDE + m] = v.z;
                As[(kb + i * 4 + 3) * AS_STRIDE + m] = v.w;
            }
        }
        {
            int kr = tid >> 4;
            int n4 = (tid & 15) * 4;
            #pragma unroll
            for (int i = 0; i < 4; i++) {
                int k = kr + i * 16;
                float4 v = *(const float4*)(Bsrc + (size_t)(k0 + k) * D + n4);
                *(float4*)&Bs[k * 64 + n4] = v;
            }
        }
        __syncthreads();
        #pragma unroll
        for (int k = 0; k < 64; k++) {
            float4 av = *(const float4*)&As[k * AS_STRIDE + ty * 4];
            float4 bv = *(const float4*)&Bs[k * 64 + tx * 4];
            float ar[4] = {av.x, av.y, av.z, av.w};
            float br[4] = {bv.x, bv.y, bv.z, bv.w};
            #pragma unroll
            for (int i = 0; i < 4; i++)
                #pragma unroll
                for (int j = 0; j < 4; j++)
                    acc[i][j] = fmaf(ar[i], br[j], acc[i][j]);
        }
        __syncthreads();
    }

    #pragma unroll
    for (int i = 0; i < 4; i++) {
        int m = bm + ty * 4 + i;
        if (m >= N_NODES) continue;
        #pragma unroll
        for (int j = 0; j < 4; j++) {
            int n = bn + tx * 4 + j;
            float v = acc[i][j];
            if (n < D) g_h[(size_t)m * D + n] = v;
            else       out[(size_t)m * D + (n - D)] = v + b_res[n - D];
        }
    }
}

// ---------------- K2: per-node scalars s1 = h.a1, s2 = h.a2 (warp per node) ----------------
__global__ void k_dots(const float* __restrict__ a) {
    int gw = (blockIdx.x * blockDim.x + threadIdx.x) >> 5;
    int lane = threadIdx.x & 31;
    if (gw >= N_NODES) return;
    float4 h4 = *(const float4*)&g_h[(size_t)gw * D + lane * 4];
    float4 a1 = *(const float4*)(a + lane * 4);
    float4 a2 = *(const float4*)(a + D + lane * 4);
    float s1 = h4.x * a1.x + h4.y * a1.y + h4.z * a1.z + h4.w * a1.w;
    float s2 = h4.x * a2.x + h4.y * a2.y + h4.z * a2.z + h4.w * a2.w;
    #pragma unroll
    for (int o = 16; o > 0; o >>= 1) {
        s1 += __shfl_xor_sync(0xFFFFFFFFu, s1, o);
        s2 += __shfl_xor_sync(0xFFFFFFFFu, s2, o);
    }
    if (lane == 0) { g_s1[gw] = s1; g_s2[gw] = s2; }
}

// ---------------- K3: histogram edges per dst ----------------
__global__ void k_hist(const int* __restrict__ ei) {
    int e = blockIdx.x * blockDim.x + threadIdx.x;
    if (e >= N_EDGES) return;
    atomicAdd(&g_cnt[ei[N_EDGES + e]], 1);
}

// ---------------- K4: single-block exclusive scan of counts -> offsets ----------------
__global__ __launch_bounds__(1024) void k_scan() {
    __shared__ int ps[1024];
    const int CH = (N_NODES + 1023) / 1024;  // 49
    int t = threadIdx.x;
    int base = t * CH;
    int s = 0;
    for (int i = 0; i < CH; i++) {
        int idx = base + i;
        if (idx < N_NODES) s += g_cnt[idx];
    }
    ps[t] = s;
    __syncthreads();
    for (int o = 1; o < 1024; o <<= 1) {
        int v = (t >= o) ? ps[t - o] : 0;
        __syncthreads();
        ps[t] += v;
        __syncthreads();
    }
    int run = (t == 0) ? 0 : ps[t - 1];
    for (int i = 0; i < CH; i++) {
        int idx = base + i;
        if (idx < N_NODES) {
            g_off[idx] = run;
            g_cur[idx] = run;
            run += g_cnt[idx];
        }
    }
}

// ---------------- K5: fill CSR with src + precomputed leakyrelu logit ----------------
__global__ void k_fill(const int* __restrict__ ei, const int* __restrict__ et) {
    int e = blockIdx.x * blockDim.x + threadIdx.x;
    if (e >= N_EDGES) return;
    int s  = ei[e];
    int dd = ei[N_EDGES + e];
    float l = g_s1[dd] + g_s2[s] + g_t[et[e]];
    l = l > 0.0f ? l : 0.2f * l;
    int pos = atomicAdd(&g_cur[dd], 1);
    g_esrc[pos] = s;
    g_elog[pos] = l;
}

// ---------------- K6: fused softmax + aggregate + residual + SELU (warp per node) ----------------
__global__ __launch_bounds__(256) void k_agg(float* __restrict__ out) {
    int node = blockIdx.x * 8 + (threadIdx.x >> 5);
    if (node >= N_NODES) return;
    int lane = threadIdx.x & 31;
    int start = g_off[node];
    int cnt   = g_cnt[node];

    float4 acc = make_float4(0.f, 0.f, 0.f, 0.f);

    if (cnt > 0) {
        if (cnt <= 32) {
            // fast path: one edge per lane
            float l = -INFINITY;
            int   s = 0;
            if (lane < cnt) {
                l = g_elog[start + lane];
                s = g_esrc[start + lane];
            }
            float m = l;
            #pragma unroll
            for (int o = 16; o > 0; o >>= 1)
                m = fmaxf(m, __shfl_xor_sync(0xFFFFFFFFu, m, o));
            float ev = (lane < cnt) ? expf(l - m) : 0.0f;
            float sum = ev;
            #pragma unroll
            for (int o = 16; o > 0; o >>= 1)
                sum += __shfl_xor_sync(0xFFFFFFFFu, sum, o);
            float al = ev / (sum + 1e-16f);
            for (int j = 0; j < cnt; j++) {
                float aj = __shfl_sync(0xFFFFFFFFu, al, j);
                int   sj = __shfl_sync(0xFFFFFFFFu, s, j);
                float4 hv = *(const float4*)&g_h[(size_t)sj * D + lane * 4];
                acc.x = fmaf(hv.x, aj, acc.x);
                acc.y = fmaf(hv.y, aj, acc.y);
                acc.z = fmaf(hv.z, aj, acc.z);
                acc.w = fmaf(hv.w, aj, acc.w);
            }
        } else {
            // general path
            float m = -INFINITY;
            for (int i = lane; i < cnt; i += 32)
                m = fmaxf(m, g_elog[start + i]);
            #pragma unroll
            for (int o = 16; o > 0; o >>= 1)
                m = fmaxf(m, __shfl_xor_sync(0xFFFFFFFFu, m, o));
            float sum = 0.0f;
            for (int i = lane; i < cnt; i += 32)
                sum += expf(g_elog[start + i] - m);
            #pragma unroll
            for (int o = 16; o > 0; o >>= 1)
                sum += __shfl_xor_sync(0xFFFFFFFFu, sum, o);
            float inv = 1.0f / (sum + 1e-16f);
            for (int i0 = 0; i0 < cnt; i0 += 32) {
                int i = i0 + lane;
                float al = 0.0f;
                int s = 0;
                if (i < cnt) {
                    al = expf(g_elog[start + i] - m) * inv;
                    s  = g_esrc[start + i];
                }
                int n = min(32, cnt - i0);
                for (int j = 0; j < n; j++) {
                    float aj = __shfl_sync(0xFFFFFFFFu, al, j);
                    int   sj = __shfl_sync(0xFFFFFFFFu, s, j);
                    float4 hv = *(const float4*)&g_h[(size_t)sj * D + lane * 4];
                    acc.x = fmaf(hv.x, aj, acc.x);
                    acc.y = fmaf(hv.y, aj, acc.y);
                    acc.z = fmaf(hv.z, aj, acc.z);
                    acc.w = fmaf(hv.w, aj, acc.w);
                }
            }
        }
    }

    // residual (already in out) + agg, then SELU, store
    const float scale  = 1.0507009873554805f;
    const float salpha = 1.7580993408473766f;
    float* o = out + (size_t)node * D + lane * 4;
    float4 r = *(float4*)o;
    r.x += acc.x; r.y += acc.y; r.z += acc.z; r.w += acc.w;
    r.x = r.x > 0.0f ? scale * r.x : salpha * expm1f(r.x);
    r.y = r.y > 0.0f ? scale * r.y : salpha * expm1f(r.y);
    r.z = r.z > 0.0f ? scale * r.z : salpha * expm1f(r.z);
    r.w = r.w > 0.0f ? scale * r.w : salpha * expm1f(r.w);
    *(float4*)o = r;
}

// ---------------- launch ----------------
extern "C" void kernel_launch(void* const* d_in, const int* in_sizes, int n_in,
                              void* d_out, int out_size) {
    const float* X      = (const float*)d_in[0];
    const int*   ei     = (const int*)  d_in[1];  // [2, E]
    const int*   et     = (const int*)  d_in[2];  // [E]
    const float* W      = (const float*)d_in[3];
    const float* W_r    = (const float*)d_in[4];
    const float* a      = (const float*)d_in[5];
    const float* W_res  = (const float*)d_in[6];
    const float* b_res  = (const float*)d_in[7];
    const float* rel    = (const float*)d_in[8];
    float* out = (float*)d_out;

    k_init<<<(N_NODES + 255) / 256, 256>>>(W_r, a, rel);

    k_hist<<<(N_EDGES + 255) / 256, 256>>>(ei);
    k_scan<<<1, 1024>>>();

    dim3 ggrid((N_NODES + 63) / 64, (2 * D) / 64);
    k_gemm<<<ggrid, 256>>>(X, W, W_res, b_res, out);

    k_dots<<<(N_NODES * 32 + 255) / 256, 256>>>(a);

    k_fill<<<(N_EDGES + 255) / 256, 256>>>(ei, et);

    k_agg<<<(N_NODES + 7) / 8, 256>>>(out);
}

// round 5
// speedup vs baseline: 2.0225x; 1.6347x over previous
#include <cuda_runtime.h>
#include <math.h>

#define N_NODES 50000
#define N_EDGES 600000
#define D 128
#define REL_DIM 100
#define N_REL 40

#define SCAN_BLOCKS ((N_NODES + 1023) / 1024)   // 49

// ---------------- device scratch ----------------
__device__ float g_h[(size_t)N_NODES * D];   // X @ W
__device__ float g_s1[N_NODES];              // h . a[:D]
__device__ float g_s2[N_NODES];              // h . a[D:2D]
__device__ float g_t[N_REL];                 // per-relation logit term
__device__ int   g_cnt[N_NODES];             // edges per dst
__device__ int   g_off[N_NODES];             // CSR start per dst
__device__ int   g_cur[N_NODES];             // fill cursor
__device__ int   g_bsum[64];                 // scan block sums
__device__ int   g_esrc[N_EDGES];            // dst-sorted src ids
__device__ float g_elog[N_EDGES];            // dst-sorted leakyrelu logits

// ---------------- f32x2 helpers ----------------
__device__ __forceinline__ unsigned long long pack2(float lo, float hi) {
    unsigned long long r;
    asm("mov.b64 %0, {%1, %2};" : "=l"(r) : "f"(lo), "f"(hi));
    return r;
}
__device__ __forceinline__ void fma2(unsigned long long& d, unsigned long long a,
                                     unsigned long long b) {
    asm("fma.rn.f32x2 %0, %1, %2, %3;" : "=l"(d) : "l"(a), "l"(b), "l"(d));
}
__device__ __forceinline__ void unpack2(unsigned long long v, float& lo, float& hi) {
    asm("mov.b64 {%0, %1}, %2;" : "=f"(lo), "=f"(hi) : "l"(v));
}

// ---------------- K0: zero counts + per-relation term t ----------------
__global__ void k_init(const float* __restrict__ W_r, const float* __restrict__ a,
                       const float* __restrict__ rel_emb) {
    int i = blockIdx.x * blockDim.x + threadIdx.x;
    if (i < N_NODES) g_cnt[i] = 0;
    if (blockIdx.x == 0) {
        __shared__ float v[REL_DIM];
        int t = threadIdx.x;
        if (t < REL_DIM) {
            float s = 0.0f;
            #pragma unroll 4
            for (int k = 0; k < D; k++) s = fmaf(W_r[t * D + k], a[2 * D + k], s);
            v[t] = s;
        }
        __syncthreads();
        if (t < N_REL) {
            float s = 0.0f;
            for (int j = 0; j < REL_DIM; j++) s = fmaf(rel_emb[t * REL_DIM + j], v[j], s);
            g_t[t] = s;
        }
    }
}

// ---------------- K1: FFMA2 SGEMM  h = X@W ; out = X@W_res + b_res ----------------
// 128x128 tile, 256 threads, 8x8 microtile, K-chunks of 16.
#define BM 128
#define BN 128
#define BK 16
#define AS_PAD 4
__global__ __launch_bounds__(256, 2) void k_gemm(const float* __restrict__ X,
                                                 const float* __restrict__ W,
                                                 const float* __restrict__ Wres,
                                                 const float* __restrict__ b_res,
                                                 float* __restrict__ out) {
    __shared__ float As[BK][BM + AS_PAD];  // [k][m]
    __shared__ float Bs[BK][BN];           // [k][n]

    int tid = threadIdx.x;
    int tx = tid & 15;         // 0..15 -> col groups
    int ty = tid >> 4;         // 0..15 -> row groups
    int bm = blockIdx.x * BM;
    const float* Bsrc = (blockIdx.y == 0) ? W : Wres;

    // A-load mapping: 128 m x 16 k / 256 threads -> 8 floats each
    int am = tid & 127;
    int ak = (tid >> 7) * 8;   // 0 or 8
    int gm = bm + am;
    // B-load mapping: 16 k x 128 n / 256 threads -> 8 floats each
    int bn4 = (tid & 31) * 4;
    int bk = tid >> 5;         // 0..7 -> rows bk, bk+8

    unsigned long long acc[8][4] = {};

    for (int k0 = 0; k0 < D; k0 += BK) {
        float4 a0 = make_float4(0.f, 0.f, 0.f, 0.f), a1 = a0;
        if (gm < N_NODES) {
            a0 = *(const float4*)(X + (size_t)gm * D + k0 + ak);
            a1 = *(const float4*)(X + (size_t)gm * D + k0 + ak + 4);
        }
        As[ak + 0][am] = a0.x; As[ak + 1][am] = a0.y;
        As[ak + 2][am] = a0.z; As[ak + 3][am] = a0.w;
        As[ak + 4][am] = a1.x; As[ak + 5][am] = a1.y;
        As[ak + 6][am] = a1.z; As[ak + 7][am] = a1.w;

        *(float4*)&Bs[bk][bn4]     = *(const float4*)(Bsrc + (size_t)(k0 + bk) * D + bn4);
        *(float4*)&Bs[bk + 8][bn4] = *(const float4*)(Bsrc + (size_t)(k0 + bk + 8) * D + bn4);
        __syncthreads();

        #pragma unroll
        for (int k = 0; k < BK; k++) {
            float4 a0v = *(const float4*)&As[k][ty * 4];
            float4 a1v = *(const float4*)&As[k][ty * 4 + 64];
            ulonglong2 b0 = *(const ulonglong2*)&Bs[k][tx * 4];
            ulonglong2 b1 = *(const ulonglong2*)&Bs[k][tx * 4 + 64];
            unsigned long long bb[4] = {b0.x, b0.y, b1.x, b1.y};
            float ar[8] = {a0v.x, a0v.y, a0v.z, a0v.w, a1v.x, a1v.y, a1v.z, a1v.w};
            #pragma unroll
            for (int i = 0; i < 8; i++) {
                unsigned long long a2 = pack2(ar[i], ar[i]);
                #pragma unroll
                for (int j = 0; j < 4; j++) fma2(acc[i][j], a2, bb[j]);
            }
        }
        __syncthreads();
    }

    // epilogue
    float4 br0 = *(const float4*)(b_res + tx * 4);
    float4 br1 = *(const float4*)(b_res + tx * 4 + 64);
    bool isW = (blockIdx.y == 0);
    #pragma unroll
    for (int i = 0; i < 8; i++) {
        int row = bm + ty * 4 + (i & 3) + ((i >= 4) ? 64 : 0);
        if (row >= N_NODES) continue;
        float c[8];
        unpack2(acc[i][0], c[0], c[1]);
        unpack2(acc[i][1], c[2], c[3]);
        unpack2(acc[i][2], c[4], c[5]);
        unpack2(acc[i][3], c[6], c[7]);
        if (isW) {
            *(float4*)&g_h[(size_t)row * D + tx * 4]      = make_float4(c[0], c[1], c[2], c[3]);
            *(float4*)&g_h[(size_t)row * D + tx * 4 + 64] = make_float4(c[4], c[5], c[6], c[7]);
        } else {
            *(float4*)(out + (size_t)row * D + tx * 4) =
                make_float4(c[0] + br0.x, c[1] + br0.y, c[2] + br0.z, c[3] + br0.w);
            *(float4*)(out + (size_t)row * D + tx * 4 + 64) =
                make_float4(c[4] + br1.x, c[5] + br1.y, c[6] + br1.z, c[7] + br1.w);
        }
    }
}

// ---------------- K2: per-node scalars s1, s2 (warp per node) ----------------
__global__ void k_dots(const float* __restrict__ a) {
    int gw = (blockIdx.x * blockDim.x + threadIdx.x) >> 5;
    int lane = threadIdx.x & 31;
    if (gw >= N_NODES) return;
    float4 h4 = *(const float4*)&g_h[(size_t)gw * D + lane * 4];
    float4 a1 = *(const float4*)(a + lane * 4);
    float4 a2 = *(const float4*)(a + D + lane * 4);
    float s1 = h4.x * a1.x + h4.y * a1.y + h4.z * a1.z + h4.w * a1.w;
    float s2 = h4.x * a2.x + h4.y * a2.y + h4.z * a2.z + h4.w * a2.w;
    #pragma unroll
    for (int o = 16; o > 0; o >>= 1) {
        s1 += __shfl_xor_sync(0xFFFFFFFFu, s1, o);
        s2 += __shfl_xor_sync(0xFFFFFFFFu, s2, o);
    }
    if (lane == 0) { g_s1[gw] = s1; g_s2[gw] = s2; }
}

// ---------------- K3: histogram ----------------
__global__ void k_hist(const int* __restrict__ ei) {
    int e = blockIdx.x * blockDim.x + threadIdx.x;
    if (e >= N_EDGES) return;
    atomicAdd(&g_cnt[ei[N_EDGES + e]], 1);
}

// ---------------- K4a/b/c: multi-block exclusive scan ----------------
__global__ __launch_bounds__(1024) void k_scan1() {
    __shared__ int sm[1024];
    int i = blockIdx.x * 1024 + threadIdx.x;
    int v = (i < N_NODES) ? g_cnt[i] : 0;
    sm[threadIdx.x] = v;
    __syncthreads();
    for (int o = 1; o < 1024; o <<= 1) {
        int t = (threadIdx.x >= o) ? sm[threadIdx.x - o] : 0;
        __syncthreads();
        sm[threadIdx.x] += t;
        __syncthreads();
    }
    if (i < N_NODES) g_off[i] = sm[threadIdx.x] - v;  // exclusive local
    if (threadIdx.x == 1023) g_bsum[blockIdx.x] = sm[1023];
}
__global__ void k_scan2() {
    if (threadIdx.x == 0) {
        int run = 0;
        for (int b = 0; b < SCAN_BLOCKS; b++) { int c = g_bsum[b]; g_bsum[b] = run; run += c; }
    }
}
__global__ __launch_bounds__(1024) void k_scan3() {
    int i = blockIdx.x * 1024 + threadIdx.x;
    if (i < N_NODES) {
        int o = g_off[i] + g_bsum[blockIdx.x];
        g_off[i] = o;
        g_cur[i] = o;
    }
}

// ---------------- K5: fill CSR with src + leakyrelu logit ----------------
__global__ void k_fill(const int* __restrict__ ei, const int* __restrict__ et) {
    int e = blockIdx.x * blockDim.x + threadIdx.x;
    if (e >= N_EDGES) return;
    int s  = ei[e];
    int dd = ei[N_EDGES + e];
    float l = g_s1[dd] + g_s2[s] + g_t[et[e]];
    l = l > 0.0f ? l : 0.2f * l;
    int pos = atomicAdd(&g_cur[dd], 1);
    g_esrc[pos] = s;
    g_elog[pos] = l;
}

// ---------------- K6: fused softmax + aggregate + residual + SELU ----------------
__global__ __launch_bounds__(256) void k_agg(float* __restrict__ out) {
    int node = blockIdx.x * 8 + (threadIdx.x >> 5);
    if (node >= N_NODES) return;
    int lane = threadIdx.x & 31;
    int start = g_off[node];
    int cnt   = g_cnt[node];

    float4 acc = make_float4(0.f, 0.f, 0.f, 0.f);

    if (cnt > 0) {
        if (cnt <= 32) {
            float l = -INFINITY;
            int   s = 0;
            if (lane < cnt) {
                l = g_elog[start + lane];
                s = g_esrc[start + lane];
            }
            float m = l;
            #pragma unroll
            for (int o = 16; o > 0; o >>= 1)
                m = fmaxf(m, __shfl_xor_sync(0xFFFFFFFFu, m, o));
            float ev = (lane < cnt) ? expf(l - m) : 0.0f;
            float sum = ev;
            #pragma unroll
            for (int o = 16; o > 0; o >>= 1)
                sum += __shfl_xor_sync(0xFFFFFFFFu, sum, o);
            float al = ev / (sum + 1e-16f);
            #pragma unroll 4
            for (int j = 0; j < cnt; j++) {
                float aj = __shfl_sync(0xFFFFFFFFu, al, j);
                int   sj = __shfl_sync(0xFFFFFFFFu, s, j);
                float4 hv = *(const float4*)&g_h[(size_t)sj * D + lane * 4];
                acc.x = fmaf(hv.x, aj, acc.x);
                acc.y = fmaf(hv.y, aj, acc.y);
                acc.z = fmaf(hv.z, aj, acc.z);
                acc.w = fmaf(hv.w, aj, acc.w);
            }
        } else {
            float m = -INFINITY;
            for (int i = lane; i < cnt; i += 32)
                m = fmaxf(m, g_elog[start + i]);
            #pragma unroll
            for (int o = 16; o > 0; o >>= 1)
                m = fmaxf(m, __shfl_xor_sync(0xFFFFFFFFu, m, o));
            float sum = 0.0f;
            for (int i = lane; i < cnt; i += 32)
                sum += expf(g_elog[start + i] - m);
            #pragma unroll
            for (int o = 16; o > 0; o >>= 1)
                sum += __shfl_xor_sync(0xFFFFFFFFu, sum, o);
            float inv = 1.0f / (sum + 1e-16f);
            for (int i0 = 0; i0 < cnt; i0 += 32) {
                int i = i0 + lane;
                float al = 0.0f;
                int s = 0;
                if (i < cnt) {
                    al = expf(g_elog[start + i] - m) * inv;
                    s  = g_esrc[start + i];
                }
                int n = min(32, cnt - i0);
                for (int j = 0; j < n; j++) {
                    float aj = __shfl_sync(0xFFFFFFFFu, al, j);
                    int   sj = __shfl_sync(0xFFFFFFFFu, s, j);
                    float4 hv = *(const float4*)&g_h[(size_t)sj * D + lane * 4];
                    acc.x = fmaf(hv.x, aj, acc.x);
                    acc.y = fmaf(hv.y, aj, acc.y);
                    acc.z = fmaf(hv.z, aj, acc.z);
                    acc.w = fmaf(hv.w, aj, acc.w);
                }
            }
        }
    }

    const float scale  = 1.0507009873554805f;
    const float salpha = 1.7580993408473766f;
    float* o = out + (size_t)node * D + lane * 4;
    float4 r = *(float4*)o;
    r.x += acc.x; r.y += acc.y; r.z += acc.z; r.w += acc.w;
    r.x = r.x > 0.0f ? scale * r.x : salpha * expm1f(r.x);
    r.y = r.y > 0.0f ? scale * r.y : salpha * expm1f(r.y);
    r.z = r.z > 0.0f ? scale * r.z : salpha * expm1f(r.z);
    r.w = r.w > 0.0f ? scale * r.w : salpha * expm1f(r.w);
    *(float4*)o = r;
}

// ---------------- launch ----------------
extern "C" void kernel_launch(void* const* d_in, const int* in_sizes, int n_in,
                              void* d_out, int out_size) {
    const float* X      = (const float*)d_in[0];
    const int*   ei     = (const int*)  d_in[1];
    const int*   et     = (const int*)  d_in[2];
    const float* W      = (const float*)d_in[3];
    const float* W_r    = (const float*)d_in[4];
    const float* a      = (const float*)d_in[5];
    const float* W_res  = (const float*)d_in[6];
    const float* b_res  = (const float*)d_in[7];
    const float* rel    = (const float*)d_in[8];
    float* out = (float*)d_out;

    k_init<<<(N_NODES + 255) / 256, 256>>>(W_r, a, rel);
    k_hist<<<(N_EDGES + 255) / 256, 256>>>(ei);
    k_scan1<<<SCAN_BLOCKS, 1024>>>();
    k_scan2<<<1, 32>>>();
    k_scan3<<<SCAN_BLOCKS, 1024>>>();

    dim3 ggrid((N_NODES + BM - 1) / BM, 2);
    k_gemm<<<ggrid, 256>>>(X, W, W_res, b_res, out);

    k_dots<<<(N_NODES * 32 + 255) / 256, 256>>>(a);
    k_fill<<<(N_EDGES + 255) / 256, 256>>>(ei, et);
    k_agg<<<(N_NODES + 7) / 8, 256>>>(out);
}

// round 6
// speedup vs baseline: 2.0439x; 1.0106x over previous
#include <cuda_runtime.h>
#include <cuda_bf16.h>
#include <math.h>

#define N_NODES 50000
#define N_EDGES 600000
#define D 128
#define REL_DIM 100
#define N_REL 40
#define SCAN_BLOCKS ((N_NODES + 1023) / 1024)   // 49
#define KTOT 384

// ---------------- device scratch ----------------
__device__ __align__(32) __nv_bfloat16 g_xh[(size_t)N_NODES * D];  // hi(X)
__device__ __align__(32) __nv_bfloat16 g_xl[(size_t)N_NODES * D];  // lo(X)
__device__ __align__(32) __nv_bfloat16 g_bt[2 * D * KTOT];         // [mat][n][k'] = [Wh;Wh;Wl]^T
__device__ float g_h[(size_t)N_NODES * D];   // X @ W
__device__ float g_s1[N_NODES];              // h . a[:D]
__device__ float g_s2[N_NODES];              // h . a[D:2D]
__device__ float g_t[N_REL];                 // per-relation logit term
__device__ int   g_cnt[N_NODES];             // edges per dst
__device__ int   g_off[N_NODES];             // CSR start per dst
__device__ int   g_cur[N_NODES];             // fill cursor
__device__ int   g_bsum[64];                 // scan block sums (raw)
__device__ int   g_esrc[N_EDGES];            // dst-sorted src ids
__device__ float g_elog[N_EDGES];            // dst-sorted leakyrelu logits

// ---------------- K_convX: split X into bf16 hi + lo ----------------
__global__ void k_convX(const float* __restrict__ X) {
    int i = blockIdx.x * blockDim.x + threadIdx.x;
    if (i >= N_NODES * D / 2) return;
    float2 v = *(const float2*)(X + (size_t)i * 2);
    __nv_bfloat16 hx = __float2bfloat16(v.x);
    __nv_bfloat16 hy = __float2bfloat16(v.y);
    __nv_bfloat16 lx = __float2bfloat16(v.x - __bfloat162float(hx));
    __nv_bfloat16 ly = __float2bfloat16(v.y - __bfloat162float(hy));
    __nv_bfloat162 hv; hv.x = hx; hv.y = hy;
    __nv_bfloat162 lv; lv.x = lx; lv.y = ly;
    *(__nv_bfloat162*)&g_xh[(size_t)i * 2] = hv;
    *(__nv_bfloat162*)&g_xl[(size_t)i * 2] = lv;
}

// ---------------- K_convB: build transposed split weights [n][k'=384] ----------------
__global__ void k_convB(const float* __restrict__ W, const float* __restrict__ Wres) {
    int idx = blockIdx.x * blockDim.x + threadIdx.x;
    if (idx >= 2 * D * D) return;
    int mat = idx >> 14;            // D*D = 16384
    int rem = idx & (D * D - 1);
    int k = rem >> 7, n = rem & 127;
    float w = (mat ? Wres : W)[k * D + n];
    __nv_bfloat16 hi = __float2bfloat16(w);
    __nv_bfloat16 lo = __float2bfloat16(w - __bfloat162float(hi));
    __nv_bfloat16* bt = g_bt + (size_t)mat * D * KTOT + (size_t)n * KTOT;
    bt[k]       = hi;   // segment 0: pairs with Xh
    bt[128 + k] = hi;   // segment 1: pairs with Xl
    bt[256 + k] = lo;   // segment 2: pairs with Xh
}

// ---------------- K0: zero counts + per-relation term t ----------------
__global__ void k_init(const float* __restrict__ W_r, const float* __restrict__ a,
                       const float* __restrict__ rel_emb) {
    int i = blockIdx.x * blockDim.x + threadIdx.x;
    if (i < N_NODES) g_cnt[i] = 0;
    if (blockIdx.x == 0) {
        __shared__ float v[REL_DIM];
        int t = threadIdx.x;
        if (t < REL_DIM) {
            float s = 0.0f;
            #pragma unroll 4
            for (int k = 0; k < D; k++) s = fmaf(W_r[t * D + k], a[2 * D + k], s);
            v[t] = s;
        }
        __syncthreads();
        if (t < N_REL) {
            float s = 0.0f;
            for (int j = 0; j < REL_DIM; j++) s = fmaf(rel_emb[t * REL_DIM + j], v[j], s);
            g_t[t] = s;
        }
    }
}

// ---------------- K1: tensor-core split-bf16 GEMM (K=384 concat) ----------------
// C[m][n] = sum_k' A'[m][k'] B'[k'][n], A' = [Xh|Xl|Xh], B' = [Wh;Wh;Wl]
// 128x128 tile, 256 threads = 8 warps (2m x 4n), warp tile 64x32 via m16n8k16.
#define ASTR 40
__global__ __launch_bounds__(256, 2) void k_gemm_t(const float* __restrict__ b_res,
                                                   float* __restrict__ out) {
    __shared__ __align__(16) __nv_bfloat16 As[128 * ASTR];
    __shared__ __align__(16) __nv_bfloat16 Bs[128 * ASTR];
    int tid = threadIdx.x;
    int bm = blockIdx.x * 128;
    int y = blockIdx.y;
    const __nv_bfloat16* Bt = g_bt + (size_t)y * D * KTOT;
    int w = tid >> 5, lane = tid & 31;
    int wm = w & 1, wn = w >> 1;
    int lr = lane >> 2, lc = (lane & 3) * 2;

    float acc[4][4][4];
    #pragma unroll
    for (int i = 0; i < 4; i++)
        #pragma unroll
        for (int j = 0; j < 4; j++)
            #pragma unroll
            for (int q = 0; q < 4; q++) acc[i][j][q] = 0.0f;

    int lm = tid & 127;
    int ls = (tid >> 7) * 16;
    int gm = bm + lm;
    bool valid = gm < N_NODES;

    for (int c = 0; c < 12; c++) {
        int kc = c * 32;
        int seg = kc >> 7;  // 0,1,2
        const __nv_bfloat16* Asrc = (seg == 1) ? g_xl : g_xh;
        int koff = (kc & 127) + ls;

        uint4 av0 = make_uint4(0, 0, 0, 0), av1 = av0;
        if (valid) {
            const uint4* p = (const uint4*)(Asrc + (size_t)gm * D + koff);
            av0 = p[0]; av1 = p[1];
        }
        const uint4* q = (const uint4*)(Bt + (size_t)lm * KTOT + kc + ls);
        uint4 bv0 = q[0], bv1 = q[1];

        __nv_bfloat16* ad = &As[lm * ASTR + ls];
        ((uint2*)ad)[0] = make_uint2(av0.x, av0.y);
        ((uint2*)ad)[1] = make_uint2(av0.z, av0.w);
        ((uint2*)ad)[2] = make_uint2(av1.x, av1.y);
        ((uint2*)ad)[3] = make_uint2(av1.z, av1.w);
        __nv_bfloat16* bd = &Bs[lm * ASTR + ls];
        ((uint2*)bd)[0] = make_uint2(bv0.x, bv0.y);
        ((uint2*)bd)[1] = make_uint2(bv0.z, bv0.w);
        ((uint2*)bd)[2] = make_uint2(bv1.x, bv1.y);
        ((uint2*)bd)[3] = make_uint2(bv1.z, bv1.w);
        __syncthreads();

        #pragma unroll
        for (int ks = 0; ks < 32; ks += 16) {
            unsigned af[4][4], bf[4][2];
            #pragma unroll
            for (int mt = 0; mt < 4; mt++) {
                int r = wm * 64 + mt * 16 + lr;
                const __nv_bfloat16* ap = &As[r * ASTR + ks + lc];
                af[mt][0] = *(const unsigned*)ap;
                af[mt][1] = *(const unsigned*)(ap + 8 * ASTR);
                af[mt][2] = *(const unsigned*)(ap + 8);
                af[mt][3] = *(const unsigned*)(ap + 8 * ASTR + 8);
            }
            #pragma unroll
            for (int nt = 0; nt < 4; nt++) {
                int n = wn * 32 + nt * 8 + lr;
                const __nv_bfloat16* bp = &Bs[n * ASTR + ks + lc];
                bf[nt][0] = *(const unsigned*)bp;
                bf[nt][1] = *(const unsigned*)(bp + 8);
            }
            #pragma unroll
            for (int mt = 0; mt < 4; mt++)
                #pragma unroll
                for (int nt = 0; nt < 4; nt++)
                    asm volatile(
                        "mma.sync.aligned.m16n8k16.row.col.f32.bf16.bf16.f32 "
                        "{%0,%1,%2,%3}, {%4,%5,%6,%7}, {%8,%9}, {%0,%1,%2,%3};"
                        : "+f"(acc[mt][nt][0]), "+f"(acc[mt][nt][1]),
                          "+f"(acc[mt][nt][2]), "+f"(acc[mt][nt][3])
                        : "r"(af[mt][0]), "r"(af[mt][1]), "r"(af[mt][2]), "r"(af[mt][3]),
                          "r"(bf[nt][0]), "r"(bf[nt][1]));
        }
        __syncthreads();
    }

    // epilogue: y==0 -> g_h ; y==1 -> out + b_res
    #pragma unroll
    for (int mt = 0; mt < 4; mt++) {
        int r0 = bm + wm * 64 + mt * 16 + lr;
        #pragma unroll
        for (int nt = 0; nt < 4; nt++) {
            int c0 = wn * 32 + nt * 8 + lc;
            if (y == 0) {
                if (r0 < N_NODES)
                    *(float2*)&g_h[(size_t)r0 * D + c0] =
                        make_float2(acc[mt][nt][0], acc[mt][nt][1]);
                if (r0 + 8 < N_NODES)
                    *(float2*)&g_h[(size_t)(r0 + 8) * D + c0] =
                        make_float2(acc[mt][nt][2], acc[mt][nt][3]);
            } else {
                float2 br = *(const float2*)(b_res + c0);
                if (r0 < N_NODES)
                    *(float2*)(out + (size_t)r0 * D + c0) =
                        make_float2(acc[mt][nt][0] + br.x, acc[mt][nt][1] + br.y);
                if (r0 + 8 < N_NODES)
                    *(float2*)(out + (size_t)(r0 + 8) * D + c0) =
                        make_float2(acc[mt][nt][2] + br.x, acc[mt][nt][3] + br.y);
            }
        }
    }
}

// ---------------- K2: per-node scalars s1, s2 (warp per node) ----------------
__global__ void k_dots(const float* __restrict__ a) {
    int gw = (blockIdx.x * blockDim.x + threadIdx.x) >> 5;
    int lane = threadIdx.x & 31;
    if (gw >= N_NODES) return;
    float4 h4 = *(const float4*)&g_h[(size_t)gw * D + lane * 4];
    float4 a1 = *(const float4*)(a + lane * 4);
    float4 a2 = *(const float4*)(a + D + lane * 4);
    float s1 = h4.x * a1.x + h4.y * a1.y + h4.z * a1.z + h4.w * a1.w;
    float s2 = h4.x * a2.x + h4.y * a2.y + h4.z * a2.z + h4.w * a2.w;
    #pragma unroll
    for (int o = 16; o > 0; o >>= 1) {
        s1 += __shfl_xor_sync(0xFFFFFFFFu, s1, o);
        s2 += __shfl_xor_sync(0xFFFFFFFFu, s2, o);
    }
    if (lane == 0) { g_s1[gw] = s1; g_s2[gw] = s2; }
}

// ---------------- K3: histogram ----------------
__global__ void k_hist(const int* __restrict__ ei) {
    int e = blockIdx.x * blockDim.x + threadIdx.x;
    if (e >= N_EDGES) return;
    atomicAdd(&g_cnt[ei[N_EDGES + e]], 1);
}

// ---------------- K4a: per-block scan, write raw block totals ----------------
__global__ __launch_bounds__(1024) void k_scan1() {
    __shared__ int sm[1024];
    int i = blockIdx.x * 1024 + threadIdx.x;
    int v = (i < N_NODES) ? g_cnt[i] : 0;
    sm[threadIdx.x] = v;
    __syncthreads();
    for (int o = 1; o < 1024; o <<= 1) {
        int t = (threadIdx.x >= o) ? sm[threadIdx.x - o] : 0;
        __syncthreads();
        sm[threadIdx.x] += t;
        __syncthreads();
    }
    if (i < N_NODES) g_off[i] = sm[threadIdx.x] - v;  // exclusive local
    if (threadIdx.x == 1023) g_bsum[blockIdx.x] = sm[1023];
}

// ---------------- K4b: add cross-block prefix (folds old scan2) ----------------
__global__ __launch_bounds__(1024) void k_scan3() {
    __shared__ int pre;
    if (threadIdx.x < 32) {
        int l = threadIdx.x;
        int v = 0;
        if (l < blockIdx.x && l < SCAN_BLOCKS) v += g_bsum[l];
        int l2 = l + 32;
        if (l2 < blockIdx.x && l2 < SCAN_BLOCKS) v += g_bsum[l2];
        #pragma unroll
        for (int o = 16; o > 0; o >>= 1) v += __shfl_xor_sync(0xFFFFFFFFu, v, o);
        if (l == 0) pre = v;
    }
    __syncthreads();
    int i = blockIdx.x * 1024 + threadIdx.x;
    if (i < N_NODES) {
        int o = g_off[i] + pre;
        g_off[i] = o;
        g_cur[i] = o;
    }
}

// ---------------- K5: fill CSR with src + leakyrelu logit ----------------
__global__ void k_fill(const int* __restrict__ ei, const int* __restrict__ et) {
    int e = blockIdx.x * blockDim.x + threadIdx.x;
    if (e >= N_EDGES) return;
    int s  = ei[e];
    int dd = ei[N_EDGES + e];
    float l = g_s1[dd] + g_s2[s] + g_t[et[e]];
    l = l > 0.0f ? l : 0.2f * l;
    int pos = atomicAdd(&g_cur[dd], 1);
    g_esrc[pos] = s;
    g_elog[pos] = l;
}

// ---------------- K6: fused softmax + aggregate + residual + SELU ----------------
__global__ __launch_bounds__(256) void k_agg(float* __restrict__ out) {
    int node = blockIdx.x * 8 + (threadIdx.x >> 5);
    if (node >= N_NODES) return;
    int lane = threadIdx.x & 31;
    int start = g_off[node];
    int cnt   = g_cnt[node];

    float4 acc = make_float4(0.f, 0.f, 0.f, 0.f);

    if (cnt > 0) {
        if (cnt <= 32) {
            float l = -INFINITY;
            int   s = 0;
            if (lane < cnt) {
                l = g_elog[start + lane];
                s = g_esrc[start + lane];
            }
            float m = l;
            #pragma unroll
            for (int o = 16; o > 0; o >>= 1)
                m = fmaxf(m, __shfl_xor_sync(0xFFFFFFFFu, m, o));
            float ev = (lane < cnt) ? expf(l - m) : 0.0f;
            float sum = ev;
            #pragma unroll
            for (int o = 16; o > 0; o >>= 1)
                sum += __shfl_xor_sync(0xFFFFFFFFu, sum, o);
            float al = ev / (sum + 1e-16f);
            #pragma unroll 4
            for (int j = 0; j < cnt; j++) {
                float aj = __shfl_sync(0xFFFFFFFFu, al, j);
                int   sj = __shfl_sync(0xFFFFFFFFu, s, j);
                float4 hv = *(const float4*)&g_h[(size_t)sj * D + lane * 4];
                acc.x = fmaf(hv.x, aj, acc.x);
                acc.y = fmaf(hv.y, aj, acc.y);
                acc.z = fmaf(hv.z, aj, acc.z);
                acc.w = fmaf(hv.w, aj, acc.w);
            }
        } else {
            float m = -INFINITY;
            for (int i = lane; i < cnt; i += 32)
                m = fmaxf(m, g_elog[start + i]);
            #pragma unroll
            for (int o = 16; o > 0; o >>= 1)
                m = fmaxf(m, __shfl_xor_sync(0xFFFFFFFFu, m, o));
            float sum = 0.0f;
            for (int i = lane; i < cnt; i += 32)
                sum += expf(g_elog[start + i] - m);
            #pragma unroll
            for (int o = 16; o > 0; o >>= 1)
                sum += __shfl_xor_sync(0xFFFFFFFFu, sum, o);
            float inv = 1.0f / (sum + 1e-16f);
            for (int i0 = 0; i0 < cnt; i0 += 32) {
                int i = i0 + lane;
                float al = 0.0f;
                int s = 0;
                if (i < cnt) {
                    al = expf(g_elog[start + i] - m) * inv;
                    s  = g_esrc[start + i];
                }
                int n = min(32, cnt - i0);
                for (int j = 0; j < n; j++) {
                    float aj = __shfl_sync(0xFFFFFFFFu, al, j);
                    int   sj = __shfl_sync(0xFFFFFFFFu, s, j);
                    float4 hv = *(const float4*)&g_h[(size_t)sj * D + lane * 4];
                    acc.x = fmaf(hv.x, aj, acc.x);
                    acc.y = fmaf(hv.y, aj, acc.y);
                    acc.z = fmaf(hv.z, aj, acc.z);
                    acc.w = fmaf(hv.w, aj, acc.w);
                }
            }
        }
    }

    const float scale  = 1.0507009873554805f;
    const float salpha = 1.7580993408473766f;
    float* o = out + (size_t)node * D + lane * 4;
    float4 r = *(float4*)o;
    r.x += acc.x; r.y += acc.y; r.z += acc.z; r.w += acc.w;
    r.x = r.x > 0.0f ? scale * r.x : salpha * expm1f(r.x);
    r.y = r.y > 0.0f ? scale * r.y : salpha * expm1f(r.y);
    r.z = r.z > 0.0f ? scale * r.z : salpha * expm1f(r.z);
    r.w = r.w > 0.0f ? scale * r.w : salpha * expm1f(r.w);
    *(float4*)o = r;
}

// ---------------- launch ----------------
extern "C" void kernel_launch(void* const* d_in, const int* in_sizes, int n_in,
                              void* d_out, int out_size) {
    const float* X      = (const float*)d_in[0];
    const int*   ei     = (const int*)  d_in[1];
    const int*   et     = (const int*)  d_in[2];
    const float* W      = (const float*)d_in[3];
    const float* W_r    = (const float*)d_in[4];
    const float* a      = (const float*)d_in[5];
    const float* W_res  = (const float*)d_in[6];
    const float* b_res  = (const float*)d_in[7];
    const float* rel    = (const float*)d_in[8];
    float* out = (float*)d_out;

    k_convX<<<(N_NODES * D / 2 + 255) / 256, 256>>>(X);
    k_convB<<<(2 * D * D + 255) / 256, 256>>>(W, W_res);
    k_init<<<(N_NODES + 255) / 256, 256>>>(W_r, a, rel);
    k_hist<<<(N_EDGES + 255) / 256, 256>>>(ei);
    k_scan1<<<SCAN_BLOCKS, 1024>>>();
    k_scan3<<<SCAN_BLOCKS, 1024>>>();

    dim3 ggrid((N_NODES + 127) / 128, 2);
    k_gemm_t<<<ggrid, 256>>>(b_res, out);

    k_dots<<<(N_NODES * 32 + 255) / 256, 256>>>(a);
    k_fill<<<(N_EDGES + 255) / 256, 256>>>(ei, et);
    k_agg<<<(N_NODES + 7) / 8, 256>>>(out);
}

// round 7
// speedup vs baseline: 2.3823x; 1.1656x over previous
#include <cuda_runtime.h>
#include <cuda_bf16.h>
#include <math.h>

#define N_NODES 50000
#define N_EDGES 600000
#define D 128
#define REL_DIM 100
#define N_REL 40
#define SCAN_BLOCKS ((N_NODES + 1023) / 1024)   // 49

// ---------------- device scratch ----------------
__device__ __align__(32) __nv_bfloat16 g_bt[4 * D * D];  // [mat][hi/lo][n][k]
__device__ float g_h[(size_t)N_NODES * D];   // X @ W
__device__ float g_s1[N_NODES];              // h . a[:D]
__device__ float g_s2[N_NODES];              // h . a[D:2D]
__device__ float g_t[N_REL];                 // per-relation logit term
__device__ int   g_cnt[N_NODES];             // edges per dst
__device__ int   g_off[N_NODES];             // CSR start per dst
__device__ int   g_cur[N_NODES];             // fill cursor
__device__ int   g_bsum[64];                 // scan block sums (raw)
__device__ int   g_esrc[N_EDGES];            // dst-sorted src ids
__device__ float g_elog[N_EDGES];            // dst-sorted leakyrelu logits

// ---------------- K_prep: zero cnt/s1/s2 + split W,Wres to bf16 hi/lo + rel term ----------------
__global__ void k_prep(const float* __restrict__ W, const float* __restrict__ Wres,
                       const float* __restrict__ W_r, const float* __restrict__ a,
                       const float* __restrict__ rel_emb) {
    int i = blockIdx.x * blockDim.x + threadIdx.x;
    if (i < N_NODES) {
        g_cnt[i] = 0;
        g_s1[i] = 0.0f;
        g_s2[i] = 0.0f;
    }
    if (i < 2 * D * D) {
        int mat = i >> 14;              // D*D = 16384
        int rem = i & (D * D - 1);
        int k = rem >> 7, n = rem & 127;
        float w = (mat ? Wres : W)[k * D + n];
        __nv_bfloat16 hi = __float2bfloat16(w);
        __nv_bfloat16 lo = __float2bfloat16(w - __bfloat162float(hi));
        g_bt[((size_t)(mat * 2 + 0) * D + n) * D + k] = hi;
        g_bt[((size_t)(mat * 2 + 1) * D + n) * D + k] = lo;
    }
    if (blockIdx.x == 0) {
        __shared__ float v[REL_DIM];
        int t = threadIdx.x;
        if (t < REL_DIM) {
            float s = 0.0f;
            #pragma unroll 4
            for (int k = 0; k < D; k++) s = fmaf(W_r[t * D + k], a[2 * D + k], s);
            v[t] = s;
        }
        __syncthreads();
        if (t < N_REL) {
            float s = 0.0f;
            for (int j = 0; j < REL_DIM; j++) s = fmaf(rel_emb[t * REL_DIM + j], v[j], s);
            g_t[t] = s;
        }
    }
}

// ---------------- K1: tensor-core split-bf16 GEMM, in-register X split ----------------
// acc += Xh*Wh + Xl*Wh + Xh*Wl per 32-wide K chunk.  128x128 tile, 8 warps.
// y==0: write g_h + accumulate s1/s2 via epilogue dot.  y==1: out = .. + b_res.
#define ASTR 40
__global__ __launch_bounds__(256, 2) void k_gemm_t(const float* __restrict__ X,
                                                   const float* __restrict__ b_res,
                                                   const float* __restrict__ a,
                                                   float* __restrict__ out) {
    __shared__ __align__(16) __nv_bfloat16 AsH[128 * ASTR];
    __shared__ __align__(16) __nv_bfloat16 AsL[128 * ASTR];
    __shared__ __align__(16) __nv_bfloat16 BsH[128 * ASTR];
    __shared__ __align__(16) __nv_bfloat16 BsL[128 * ASTR];
    int tid = threadIdx.x;
    int bm = blockIdx.x * 128;
    int y = blockIdx.y;
    const __nv_bfloat16* BtH = g_bt + (size_t)(y * 2 + 0) * D * D;
    const __nv_bfloat16* BtL = g_bt + (size_t)(y * 2 + 1) * D * D;
    int w = tid >> 5, lane = tid & 31;
    int wm = w & 1, wn = w >> 1;
    int lr = lane >> 2, lc = (lane & 3) * 2;

    float acc[4][4][4];
    #pragma unroll
    for (int i = 0; i < 4; i++)
        #pragma unroll
        for (int j = 0; j < 4; j++)
            #pragma unroll
            for (int q = 0; q < 4; q++) acc[i][j][q] = 0.0f;

    int lm = tid & 127;            // row (m for A, n for B)
    int ls = (tid >> 7) * 16;      // k sub-offset 0 / 16
    int gm = bm + lm;
    bool valid = gm < N_NODES;

    for (int kc = 0; kc < D; kc += 32) {
        // ---- A: load 16 fp32, split into hi/lo bf16 in-register ----
        float f[16];
        #pragma unroll
        for (int i = 0; i < 4; i++) {
            float4 v = make_float4(0.f, 0.f, 0.f, 0.f);
            if (valid) v = *(const float4*)(X + (size_t)gm * D + kc + ls + i * 4);
            f[i * 4 + 0] = v.x; f[i * 4 + 1] = v.y; f[i * 4 + 2] = v.z; f[i * 4 + 3] = v.w;
        }
        unsigned hp[8], lp[8];
        #pragma unroll
        for (int j = 0; j < 8; j++) {
            __nv_bfloat16 h0 = __float2bfloat16(f[2 * j]);
            __nv_bfloat16 h1 = __float2bfloat16(f[2 * j + 1]);
            float l0 = f[2 * j] - __bfloat162float(h0);
            float l1 = f[2 * j + 1] - __bfloat162float(h1);
            __nv_bfloat16 e0 = __float2bfloat16(l0);
            __nv_bfloat16 e1 = __float2bfloat16(l1);
            hp[j] = ((unsigned)__bfloat16_as_ushort(h1) << 16) | __bfloat16_as_ushort(h0);
            lp[j] = ((unsigned)__bfloat16_as_ushort(e1) << 16) | __bfloat16_as_ushort(e0);
        }
        __nv_bfloat16* ah = &AsH[lm * ASTR + ls];
        __nv_bfloat16* al = &AsL[lm * ASTR + ls];
        #pragma unroll
        for (int j = 0; j < 4; j++) {
            ((uint2*)ah)[j] = make_uint2(hp[2 * j], hp[2 * j + 1]);
            ((uint2*)al)[j] = make_uint2(lp[2 * j], lp[2 * j + 1]);
        }
        // ---- B: copy hi/lo chunks ----
        {
            const uint4* qh = (const uint4*)(BtH + (size_t)lm * D + kc + ls);
            const uint4* ql = (const uint4*)(BtL + (size_t)lm * D + kc + ls);
            uint4 h0 = qh[0], h1 = qh[1], l0 = ql[0], l1 = ql[1];
            __nv_bfloat16* bh = &BsH[lm * ASTR + ls];
            __nv_bfloat16* bl = &BsL[lm * ASTR + ls];
            ((uint2*)bh)[0] = make_uint2(h0.x, h0.y);
            ((uint2*)bh)[1] = make_uint2(h0.z, h0.w);
            ((uint2*)bh)[2] = make_uint2(h1.x, h1.y);
            ((uint2*)bh)[3] = make_uint2(h1.z, h1.w);
            ((uint2*)bl)[0] = make_uint2(l0.x, l0.y);
            ((uint2*)bl)[1] = make_uint2(l0.z, l0.w);
            ((uint2*)bl)[2] = make_uint2(l1.x, l1.y);
            ((uint2*)bl)[3] = make_uint2(l1.z, l1.w);
        }
        __syncthreads();

        #pragma unroll
        for (int ks = 0; ks < 32; ks += 16) {
            unsigned afH[4][4], bfH[4][2], bfL[4][2];
            #pragma unroll
            for (int mt = 0; mt < 4; mt++) {
                int r = wm * 64 + mt * 16 + lr;
                const __nv_bfloat16* ap = &AsH[r * ASTR + ks + lc];
                afH[mt][0] = *(const unsigned*)ap;
                afH[mt][1] = *(const unsigned*)(ap + 8 * ASTR);
                afH[mt][2] = *(const unsigned*)(ap + 8);
                afH[mt][3] = *(const unsigned*)(ap + 8 * ASTR + 8);
            }
            #pragma unroll
            for (int nt = 0; nt < 4; nt++) {
                int n = wn * 32 + nt * 8 + lr;
                const __nv_bfloat16* bp = &BsH[n * ASTR + ks + lc];
                bfH[nt][0] = *(const unsigned*)bp;
                bfH[nt][1] = *(const unsigned*)(bp + 8);
                const __nv_bfloat16* bq = &BsL[n * ASTR + ks + lc];
                bfL[nt][0] = *(const unsigned*)bq;
                bfL[nt][1] = *(const unsigned*)(bq + 8);
            }
            // Xh*Wh and Xh*Wl
            #pragma unroll
            for (int mt = 0; mt < 4; mt++)
                #pragma unroll
                for (int nt = 0; nt < 4; nt++) {
                    asm volatile(
                        "mma.sync.aligned.m16n8k16.row.col.f32.bf16.bf16.f32 "
                        "{%0,%1,%2,%3}, {%4,%5,%6,%7}, {%8,%9}, {%0,%1,%2,%3};"
                        : "+f"(acc[mt][nt][0]), "+f"(acc[mt][nt][1]),
                          "+f"(acc[mt][nt][2]), "+f"(acc[mt][nt][3])
                        : "r"(afH[mt][0]), "r"(afH[mt][1]), "r"(afH[mt][2]), "r"(afH[mt][3]),
                          "r"(bfH[nt][0]), "r"(bfH[nt][1]));
                    asm volatile(
                        "mma.sync.aligned.m16n8k16.row.col.f32.bf16.bf16.f32 "
                        "{%0,%1,%2,%3}, {%4,%5,%6,%7}, {%8,%9}, {%0,%1,%2,%3};"
                        : "+f"(acc[mt][nt][0]), "+f"(acc[mt][nt][1]),
                          "+f"(acc[mt][nt][2]), "+f"(acc[mt][nt][3])
                        : "r"(afH[mt][0]), "r"(afH[mt][1]), "r"(afH[mt][2]), "r"(afH[mt][3]),
                          "r"(bfL[nt][0]), "r"(bfL[nt][1]));
                }
            // Xl*Wh (reload A frags from AsL, reuse bfH)
            #pragma unroll
            for (int mt = 0; mt < 4; mt++) {
                int r = wm * 64 + mt * 16 + lr;
                const __nv_bfloat16* ap = &AsL[r * ASTR + ks + lc];
                unsigned a0 = *(const unsigned*)ap;
                unsigned a1 = *(const unsigned*)(ap + 8 * ASTR);
                unsigned a2 = *(const unsigned*)(ap + 8);
                unsigned a3 = *(const unsigned*)(ap + 8 * ASTR + 8);
                #pragma unroll
                for (int nt = 0; nt < 4; nt++)
                    asm volatile(
                        "mma.sync.aligned.m16n8k16.row.col.f32.bf16.bf16.f32 "
                        "{%0,%1,%2,%3}, {%4,%5,%6,%7}, {%8,%9}, {%0,%1,%2,%3};"
                        : "+f"(acc[mt][nt][0]), "+f"(acc[mt][nt][1]),
                          "+f"(acc[mt][nt][2]), "+f"(acc[mt][nt][3])
                        : "r"(a0), "r"(a1), "r"(a2), "r"(a3),
                          "r"(bfH[nt][0]), "r"(bfH[nt][1]));
            }
        }
        __syncthreads();
    }

    if (y == 0) {
        // write g_h + fused s1/s2 partial dots
        #pragma unroll
        for (int mt = 0; mt < 4; mt++) {
            int r0 = bm + wm * 64 + mt * 16 + lr;
            float p1a = 0.f, p2a = 0.f, p1b = 0.f, p2b = 0.f;
            #pragma unroll
            for (int nt = 0; nt < 4; nt++) {
                int c0 = wn * 32 + nt * 8 + lc;
                float a1x = a[c0], a1y = a[c0 + 1];
                float a2x = a[D + c0], a2y = a[D + c0 + 1];
                if (r0 < N_NODES)
                    *(float2*)&g_h[(size_t)r0 * D + c0] =
                        make_float2(acc[mt][nt][0], acc[mt][nt][1]);
                if (r0 + 8 < N_NODES)
                    *(float2*)&g_h[(size_t)(r0 + 8) * D + c0] =
                        make_float2(acc[mt][nt][2], acc[mt][nt][3]);
                p1a = fmaf(acc[mt][nt][0], a1x, fmaf(acc[mt][nt][1], a1y, p1a));
                p2a = fmaf(acc[mt][nt][0], a2x, fmaf(acc[mt][nt][1], a2y, p2a));
                p1b = fmaf(acc[mt][nt][2], a1x, fmaf(acc[mt][nt][3], a1y, p1b));
                p2b = fmaf(acc[mt][nt][2], a2x, fmaf(acc[mt][nt][3], a2y, p2b));
            }
            // reduce over the 4 lanes sharing this row (lane & 3)
            #pragma unroll
            for (int o = 1; o <= 2; o <<= 1) {
                p1a += __shfl_xor_sync(0xFFFFFFFFu, p1a, o);
                p2a += __shfl_xor_sync(0xFFFFFFFFu, p2a, o);
                p1b += __shfl_xor_sync(0xFFFFFFFFu, p1b, o);
                p2b += __shfl_xor_sync(0xFFFFFFFFu, p2b, o);
            }
            if ((lane & 3) == 0) {
                if (r0 < N_NODES) {
                    atomicAdd(&g_s1[r0], p1a);
                    atomicAdd(&g_s2[r0], p2a);
                }
                if (r0 + 8 < N_NODES) {
                    atomicAdd(&g_s1[r0 + 8], p1b);
                    atomicAdd(&g_s2[r0 + 8], p2b);
                }
            }
        }
    } else {
        #pragma unroll
        for (int mt = 0; mt < 4; mt++) {
            int r0 = bm + wm * 64 + mt * 16 + lr;
            #pragma unroll
            for (int nt = 0; nt < 4; nt++) {
                int c0 = wn * 32 + nt * 8 + lc;
                float2 br = *(const float2*)(b_res + c0);
                if (r0 < N_NODES)
                    *(float2*)(out + (size_t)r0 * D + c0) =
                        make_float2(acc[mt][nt][0] + br.x, acc[mt][nt][1] + br.y);
                if (r0 + 8 < N_NODES)
                    *(float2*)(out + (size_t)(r0 + 8) * D + c0) =
                        make_float2(acc[mt][nt][2] + br.x, acc[mt][nt][3] + br.y);
            }
        }
    }
}

// ---------------- K3: histogram (2 edges / thread) ----------------
__global__ void k_hist(const int* __restrict__ ei) {
    int i = blockIdx.x * blockDim.x + threadIdx.x;
    if (i >= N_EDGES / 2) return;
    int2 d = *(const int2*)(ei + N_EDGES + 2 * i);
    atomicAdd(&g_cnt[d.x], 1);
    atomicAdd(&g_cnt[d.y], 1);
}

// ---------------- K4a: per-block scan, write raw block totals ----------------
__global__ __launch_bounds__(1024) void k_scan1() {
    __shared__ int sm[1024];
    int i = blockIdx.x * 1024 + threadIdx.x;
    int v = (i < N_NODES) ? g_cnt[i] : 0;
    sm[threadIdx.x] = v;
    __syncthreads();
    for (int o = 1; o < 1024; o <<= 1) {
        int t = (threadIdx.x >= o) ? sm[threadIdx.x - o] : 0;
        __syncthreads();
        sm[threadIdx.x] += t;
        __syncthreads();
    }
    if (i < N_NODES) g_off[i] = sm[threadIdx.x] - v;
    if (threadIdx.x == 1023) g_bsum[blockIdx.x] = sm[1023];
}

// ---------------- K4b: add cross-block prefix ----------------
__global__ __launch_bounds__(1024) void k_scan3() {
    __shared__ int pre;
    if (threadIdx.x < 32) {
        int l = threadIdx.x;
        int v = 0;
        if (l < blockIdx.x && l < SCAN_BLOCKS) v += g_bsum[l];
        int l2 = l + 32;
        if (l2 < blockIdx.x && l2 < SCAN_BLOCKS) v += g_bsum[l2];
        #pragma unroll
        for (int o = 16; o > 0; o >>= 1) v += __shfl_xor_sync(0xFFFFFFFFu, v, o);
        if (l == 0) pre = v;
    }
    __syncthreads();
    int i = blockIdx.x * 1024 + threadIdx.x;
    if (i < N_NODES) {
        int o = g_off[i] + pre;
        g_off[i] = o;
        g_cur[i] = o;
    }
}

// ---------------- K5: fill CSR with src + leakyrelu logit ----------------
__global__ void k_fill(const int* __restrict__ ei, const int* __restrict__ et) {
    int e = blockIdx.x * blockDim.x + threadIdx.x;
    if (e >= N_EDGES) return;
    int s  = ei[e];
    int dd = ei[N_EDGES + e];
    float l = g_s1[dd] + g_s2[s] + g_t[et[e]];
    l = l > 0.0f ? l : 0.2f * l;
    int pos = atomicAdd(&g_cur[dd], 1);
    g_esrc[pos] = s;
    g_elog[pos] = l;
}

// ---------------- K6: fused softmax + aggregate + residual + SELU ----------------
__global__ __launch_bounds__(256) void k_agg(float* __restrict__ out) {
    int node = blockIdx.x * 8 + (threadIdx.x >> 5);
    if (node >= N_NODES) return;
    int lane = threadIdx.x & 31;
    int start = g_off[node];
    int cnt   = g_cnt[node];

    float4 acc = make_float4(0.f, 0.f, 0.f, 0.f);

    if (cnt > 0) {
        if (cnt <= 32) {
            float l = -INFINITY;
            int   s = 0;
            if (lane < cnt) {
                l = g_elog[start + lane];
                s = g_esrc[start + lane];
            }
            float m = l;
            #pragma unroll
            for (int o = 16; o > 0; o >>= 1)
                m = fmaxf(m, __shfl_xor_sync(0xFFFFFFFFu, m, o));
            float ev = (lane < cnt) ? __expf(l - m) : 0.0f;
            float sum = ev;
            #pragma unroll
            for (int o = 16; o > 0; o >>= 1)
                sum += __shfl_xor_sync(0xFFFFFFFFu, sum, o);
            float al = ev / (sum + 1e-16f);
            #pragma unroll 4
            for (int j = 0; j < cnt; j++) {
                float aj = __shfl_sync(0xFFFFFFFFu, al, j);
                int   sj = __shfl_sync(0xFFFFFFFFu, s, j);
                float4 hv = *(const float4*)&g_h[(size_t)sj * D + lane * 4];
                acc.x = fmaf(hv.x, aj, acc.x);
                acc.y = fmaf(hv.y, aj, acc.y);
                acc.z = fmaf(hv.z, aj, acc.z);
                acc.w = fmaf(hv.w, aj, acc.w);
            }
        } else {
            float m = -INFINITY;
            for (int i = lane; i < cnt; i += 32)
                m = fmaxf(m, g_elog[start + i]);
            #pragma unroll
            for (int o = 16; o > 0; o >>= 1)
                m = fmaxf(m, __shfl_xor_sync(0xFFFFFFFFu, m, o));
            float sum = 0.0f;
            for (int i = lane; i < cnt; i += 32)
                sum += __expf(g_elog[start + i] - m);
            #pragma unroll
            for (int o = 16; o > 0; o >>= 1)
                sum += __shfl_xor_sync(0xFFFFFFFFu, sum, o);
            float inv = 1.0f / (sum + 1e-16f);
            for (int i0 = 0; i0 < cnt; i0 += 32) {
                int i = i0 + lane;
                float al = 0.0f;
                int s = 0;
                if (i < cnt) {
                    al = __expf(g_elog[start + i] - m) * inv;
                    s  = g_esrc[start + i];
                }
                int n = min(32, cnt - i0);
                #pragma unroll 4
                for (int j = 0; j < n; j++) {
                    float aj = __shfl_sync(0xFFFFFFFFu, al, j);
                    int   sj = __shfl_sync(0xFFFFFFFFu, s, j);
                    float4 hv = *(const float4*)&g_h[(size_t)sj * D + lane * 4];
                    acc.x = fmaf(hv.x, aj, acc.x);
                    acc.y = fmaf(hv.y, aj, acc.y);
                    acc.z = fmaf(hv.z, aj, acc.z);
                    acc.w = fmaf(hv.w, aj, acc.w);
                }
            }
        }
    }

    const float scale  = 1.0507009873554805f;
    const float salpha = 1.7580993408473766f;
    float* o = out + (size_t)node * D + lane * 4;
    float4 r = *(float4*)o;
    r.x += acc.x; r.y += acc.y; r.z += acc.z; r.w += acc.w;
    r.x = r.x > 0.0f ? scale * r.x : salpha * expm1f(r.x);
    r.y = r.y > 0.0f ? scale * r.y : salpha * expm1f(r.y);
    r.z = r.z > 0.0f ? scale * r.z : salpha * expm1f(r.z);
    r.w = r.w > 0.0f ? scale * r.w : salpha * expm1f(r.w);
    *(float4*)o = r;
}

// ---------------- launch ----------------
extern "C" void kernel_launch(void* const* d_in, const int* in_sizes, int n_in,
                              void* d_out, int out_size) {
    const float* X      = (const float*)d_in[0];
    const int*   ei     = (const int*)  d_in[1];
    const int*   et     = (const int*)  d_in[2];
    const float* W      = (const float*)d_in[3];
    const float* W_r    = (const float*)d_in[4];
    const float* a      = (const float*)d_in[5];
    const float* W_res  = (const float*)d_in[6];
    const float* b_res  = (const float*)d_in[7];
    const float* rel    = (const float*)d_in[8];
    float* out = (float*)d_out;

    k_prep<<<(N_NODES + 255) / 256, 256>>>(W, W_res, W_r, a, rel);
    k_hist<<<(N_EDGES / 2 + 255) / 256, 256>>>(ei);
    k_scan1<<<SCAN_BLOCKS, 1024>>>();
    k_scan3<<<SCAN_BLOCKS, 1024>>>();

    dim3 ggrid((N_NODES + 127) / 128, 2);
    k_gemm_t<<<ggrid, 256>>>(X, b_res, a, out);

    k_fill<<<(N_EDGES + 255) / 256, 256>>>(ei, et);
    k_agg<<<(N_NODES + 7) / 8, 256>>>(out);
}

// round 8
// speedup vs baseline: 2.6518x; 1.1131x over previous
#include <cuda_runtime.h>
#include <cuda_bf16.h>
#include <math.h>

#define N_NODES 50000
#define N_EDGES 600000
#define D 128
#define REL_DIM 100
#define N_REL 40

// ---------------- device scratch ----------------
__device__ __align__(32) __nv_bfloat16 g_bt[4 * D * D];  // [mat][hi/lo][n][k]
__device__ float g_h[(size_t)N_NODES * D];   // X @ W
__device__ float g_s1[N_NODES];              // h . a[:D]
__device__ float g_s2[N_NODES];              // h . a[D:2D]
__device__ float g_t[N_REL];                 // per-relation logit term
__device__ int   g_cnt[N_NODES];             // edges per dst
__device__ int   g_off[N_NODES];             // CSR segment base per dst
__device__ int   g_cur[N_NODES];             // fill cursor
__device__ int   g_ctr;                      // global bump allocator
__device__ unsigned g_epack[N_EDGES];        // dst-grouped: src | (etype<<16)

// ---------------- K_prep: zero state + split W,Wres to bf16 hi/lo + rel term ----------------
__global__ void k_prep(const float* __restrict__ W, const float* __restrict__ Wres,
                       const float* __restrict__ W_r, const float* __restrict__ a,
                       const float* __restrict__ rel_emb) {
    int i = blockIdx.x * blockDim.x + threadIdx.x;
    if (i == 0) g_ctr = 0;
    if (i < N_NODES) {
        g_cnt[i] = 0;
        g_s1[i] = 0.0f;
        g_s2[i] = 0.0f;
    }
    if (i < 2 * D * D) {
        int mat = i >> 14;              // D*D = 16384
        int rem = i & (D * D - 1);
        int k = rem >> 7, n = rem & 127;
        float w = (mat ? Wres : W)[k * D + n];
        __nv_bfloat16 hi = __float2bfloat16(w);
        __nv_bfloat16 lo = __float2bfloat16(w - __bfloat162float(hi));
        g_bt[((size_t)(mat * 2 + 0) * D + n) * D + k] = hi;
        g_bt[((size_t)(mat * 2 + 1) * D + n) * D + k] = lo;
    }
    if (blockIdx.x == 0) {
        __shared__ float v[REL_DIM];
        int t = threadIdx.x;
        if (t < REL_DIM) {
            float s = 0.0f;
            #pragma unroll 4
            for (int k = 0; k < D; k++) s = fmaf(W_r[t * D + k], a[2 * D + k], s);
            v[t] = s;
        }
        __syncthreads();
        if (t < N_REL) {
            float s = 0.0f;
            for (int j = 0; j < REL_DIM; j++) s = fmaf(rel_emb[t * REL_DIM + j], v[j], s);
            g_t[t] = s;
        }
    }
}

// ---------------- K_hist: edges per dst (2 edges / thread) ----------------
__global__ void k_hist(const int* __restrict__ ei) {
    int i = blockIdx.x * blockDim.x + threadIdx.x;
    if (i >= N_EDGES / 2) return;
    int2 d = *(const int2*)(ei + N_EDGES + 2 * i);
    atomicAdd(&g_cnt[d.x], 1);
    atomicAdd(&g_cnt[d.y], 1);
}

// ---------------- K_alloc: bump-allocate CSR segments (placement order irrelevant) ----------------
__global__ __launch_bounds__(1024) void k_alloc() {
    __shared__ int wsum[32];
    __shared__ int bbase;
    int i = blockIdx.x * 1024 + threadIdx.x;
    int lane = threadIdx.x & 31, wid = threadIdx.x >> 5;
    int c = (i < N_NODES) ? g_cnt[i] : 0;
    int p = c;
    #pragma unroll
    for (int o = 1; o < 32; o <<= 1) {
        int v = __shfl_up_sync(0xFFFFFFFFu, p, o);
        if (lane >= o) p += v;
    }
    if (lane == 31) wsum[wid] = p;
    __syncthreads();
    if (wid == 0) {
        int v = wsum[lane];
        int q = v;
        #pragma unroll
        for (int o = 1; o < 32; o <<= 1) {
            int u = __shfl_up_sync(0xFFFFFFFFu, q, o);
            if (lane >= o) q += u;
        }
        wsum[lane] = q - v;                 // exclusive warp base
        if (lane == 31) bbase = atomicAdd(&g_ctr, q);  // block total
    }
    __syncthreads();
    if (i < N_NODES) {
        int base = bbase + wsum[wid] + (p - c);
        g_off[i] = base;
        g_cur[i] = base;
    }
}

// ---------------- K_fill: scatter packed (src | et<<16) into CSR ----------------
__global__ void k_fill(const int* __restrict__ ei, const int* __restrict__ et) {
    int e = blockIdx.x * blockDim.x + threadIdx.x;
    if (e >= N_EDGES) return;
    int s  = ei[e];
    int dd = ei[N_EDGES + e];
    int pos = atomicAdd(&g_cur[dd], 1);
    g_epack[pos] = (unsigned)s | ((unsigned)et[e] << 16);
}

// ---------------- ldmatrix helpers ----------------
__device__ __forceinline__ unsigned smem_u32(const void* p) {
    return (unsigned)__cvta_generic_to_shared(p);
}
__device__ __forceinline__ void ldsm_x4(unsigned& r0, unsigned& r1, unsigned& r2,
                                        unsigned& r3, unsigned addr) {
    asm volatile("ldmatrix.sync.aligned.m8n8.x4.shared.b16 {%0,%1,%2,%3}, [%4];"
                 : "=r"(r0), "=r"(r1), "=r"(r2), "=r"(r3) : "r"(addr));
}

// ---------------- K1: tensor-core split-bf16 GEMM (ldmatrix frags) ----------------
#define ASTR 40
__global__ __launch_bounds__(256, 2) void k_gemm_t(const float* __restrict__ X,
                                                   const float* __restrict__ b_res,
                                                   const float* __restrict__ a,
                                                   float* __restrict__ out) {
    __shared__ __align__(16) __nv_bfloat16 AsH[128 * ASTR];
    __shared__ __align__(16) __nv_bfloat16 AsL[128 * ASTR];
    __shared__ __align__(16) __nv_bfloat16 BsH[128 * ASTR];
    __shared__ __align__(16) __nv_bfloat16 BsL[128 * ASTR];
    int tid = threadIdx.x;
    int bm = blockIdx.x * 128;
    int y = blockIdx.y;
    const __nv_bfloat16* BtH = g_bt + (size_t)(y * 2 + 0) * D * D;
    const __nv_bfloat16* BtL = g_bt + (size_t)(y * 2 + 1) * D * D;
    int w = tid >> 5, lane = tid & 31;
    int wm = w & 1, wn = w >> 1;
    int lr = lane >> 2, lc = (lane & 3) * 2;

    float acc[4][4][4];
    #pragma unroll
    for (int i = 0; i < 4; i++)
        #pragma unroll
        for (int j = 0; j < 4; j++)
            #pragma unroll
            for (int q = 0; q < 4; q++) acc[i][j][q] = 0.0f;

    int lm = tid & 127;
    int ls = (tid >> 7) * 16;
    int gm = bm + lm;
    bool valid = gm < N_NODES;

    // ldmatrix lane address components
    int arow = lane & 15;
    int acol = (lane >> 4) * 8;
    int nrow = (lane & 7) + ((lane >> 4) & 1) * 8;
    int kcol = ((lane >> 3) & 1) * 8;

    for (int kc = 0; kc < D; kc += 32) {
        // ---- A: load 16 fp32, split hi/lo in-register ----
        float f[16];
        #pragma unroll
        for (int i = 0; i < 4; i++) {
            float4 v = make_float4(0.f, 0.f, 0.f, 0.f);
            if (valid) v = *(const float4*)(X + (size_t)gm * D + kc + ls + i * 4);
            f[i * 4 + 0] = v.x; f[i * 4 + 1] = v.y; f[i * 4 + 2] = v.z; f[i * 4 + 3] = v.w;
        }
        unsigned hp[8], lp[8];
        #pragma unroll
        for (int j = 0; j < 8; j++) {
            __nv_bfloat16 h0 = __float2bfloat16(f[2 * j]);
            __nv_bfloat16 h1 = __float2bfloat16(f[2 * j + 1]);
            __nv_bfloat16 e0 = __float2bfloat16(f[2 * j] - __bfloat162float(h0));
            __nv_bfloat16 e1 = __float2bfloat16(f[2 * j + 1] - __bfloat162float(h1));
            hp[j] = ((unsigned)__bfloat16_as_ushort(h1) << 16) | __bfloat16_as_ushort(h0);
            lp[j] = ((unsigned)__bfloat16_as_ushort(e1) << 16) | __bfloat16_as_ushort(e0);
        }
        __nv_bfloat16* ah = &AsH[lm * ASTR + ls];
        __nv_bfloat16* al = &AsL[lm * ASTR + ls];
        #pragma unroll
        for (int j = 0; j < 4; j++) {
            ((uint2*)ah)[j] = make_uint2(hp[2 * j], hp[2 * j + 1]);
            ((uint2*)al)[j] = make_uint2(lp[2 * j], lp[2 * j + 1]);
        }
        // ---- B: copy hi/lo chunks ----
        {
            const uint4* qh = (const uint4*)(BtH + (size_t)lm * D + kc + ls);
            const uint4* ql = (const uint4*)(BtL + (size_t)lm * D + kc + ls);
            uint4 h0 = qh[0], h1 = qh[1], l0 = ql[0], l1 = ql[1];
            __nv_bfloat16* bh = &BsH[lm * ASTR + ls];
            __nv_bfloat16* bl = &BsL[lm * ASTR + ls];
            ((uint2*)bh)[0] = make_uint2(h0.x, h0.y);
            ((uint2*)bh)[1] = make_uint2(h0.z, h0.w);
            ((uint2*)bh)[2] = make_uint2(h1.x, h1.y);
            ((uint2*)bh)[3] = make_uint2(h1.z, h1.w);
            ((uint2*)bl)[0] = make_uint2(l0.x, l0.y);
            ((uint2*)bl)[1] = make_uint2(l0.z, l0.w);
            ((uint2*)bl)[2] = make_uint2(l1.x, l1.y);
            ((uint2*)bl)[3] = make_uint2(l1.z, l1.w);
        }
        __syncthreads();

        #pragma unroll
        for (int ks = 0; ks < 32; ks += 16) {
            unsigned afH[4][4], bfH[4][2], bfL[4][2];
            #pragma unroll
            for (int mt = 0; mt < 4; mt++) {
                unsigned ad = smem_u32(&AsH[(wm * 64 + mt * 16 + arow) * ASTR + ks + acol]);
                ldsm_x4(afH[mt][0], afH[mt][1], afH[mt][2], afH[mt][3], ad);
            }
            #pragma unroll
            for (int p = 0; p < 2; p++) {
                unsigned bdh = smem_u32(&BsH[(wn * 32 + p * 16 + nrow) * ASTR + ks + kcol]);
                ldsm_x4(bfH[2 * p][0], bfH[2 * p][1], bfH[2 * p + 1][0], bfH[2 * p + 1][1], bdh);
                unsigned bdl = smem_u32(&BsL[(wn * 32 + p * 16 + nrow) * ASTR + ks + kcol]);
                ldsm_x4(bfL[2 * p][0], bfL[2 * p][1], bfL[2 * p + 1][0], bfL[2 * p + 1][1], bdl);
            }
            // Xh*Wh + Xh*Wl
            #pragma unroll
            for (int mt = 0; mt < 4; mt++)
                #pragma unroll
                for (int nt = 0; nt < 4; nt++) {
                    asm volatile(
                        "mma.sync.aligned.m16n8k16.row.col.f32.bf16.bf16.f32 "
                        "{%0,%1,%2,%3}, {%4,%5,%6,%7}, {%8,%9}, {%0,%1,%2,%3};"
                        : "+f"(acc[mt][nt][0]), "+f"(acc[mt][nt][1]),
                          "+f"(acc[mt][nt][2]), "+f"(acc[mt][nt][3])
                        : "r"(afH[mt][0]), "r"(afH[mt][1]), "r"(afH[mt][2]), "r"(afH[mt][3]),
                          "r"(bfH[nt][0]), "r"(bfH[nt][1]));
                    asm volatile(
                        "mma.sync.aligned.m16n8k16.row.col.f32.bf16.bf16.f32 "
                        "{%0,%1,%2,%3}, {%4,%5,%6,%7}, {%8,%9}, {%0,%1,%2,%3};"
                        : "+f"(acc[mt][nt][0]), "+f"(acc[mt][nt][1]),
                          "+f"(acc[mt][nt][2]), "+f"(acc[mt][nt][3])
                        : "r"(afH[mt][0]), "r"(afH[mt][1]), "r"(afH[mt][2]), "r"(afH[mt][3]),
                          "r"(bfL[nt][0]), "r"(bfL[nt][1]));
                }
            // Xl*Wh
            #pragma unroll
            for (int mt = 0; mt < 4; mt++) {
                unsigned a0, a1, a2, a3;
                unsigned ad = smem_u32(&AsL[(wm * 64 + mt * 16 + arow) * ASTR + ks + acol]);
                ldsm_x4(a0, a1, a2, a3, ad);
                #pragma unroll
                for (int nt = 0; nt < 4; nt++)
                    asm volatile(
                        "mma.sync.aligned.m16n8k16.row.col.f32.bf16.bf16.f32 "
                        "{%0,%1,%2,%3}, {%4,%5,%6,%7}, {%8,%9}, {%0,%1,%2,%3};"
                        : "+f"(acc[mt][nt][0]), "+f"(acc[mt][nt][1]),
                          "+f"(acc[mt][nt][2]), "+f"(acc[mt][nt][3])
                        : "r"(a0), "r"(a1), "r"(a2), "r"(a3),
                          "r"(bfH[nt][0]), "r"(bfH[nt][1]));
            }
        }
        __syncthreads();
    }

    if (y == 0) {
        #pragma unroll
        for (int mt = 0; mt < 4; mt++) {
            int r0 = bm + wm * 64 + mt * 16 + lr;
            float p1a = 0.f, p2a = 0.f, p1b = 0.f, p2b = 0.f;
            #pragma unroll
            for (int nt = 0; nt < 4; nt++) {
                int c0 = wn * 32 + nt * 8 + lc;
                float a1x = a[c0], a1y = a[c0 + 1];
                float a2x = a[D + c0], a2y = a[D + c0 + 1];
                if (r0 < N_NODES)
                    *(float2*)&g_h[(size_t)r0 * D + c0] =
                        make_float2(acc[mt][nt][0], acc[mt][nt][1]);
                if (r0 + 8 < N_NODES)
                    *(float2*)&g_h[(size_t)(r0 + 8) * D + c0] =
                        make_float2(acc[mt][nt][2], acc[mt][nt][3]);
                p1a = fmaf(acc[mt][nt][0], a1x, fmaf(acc[mt][nt][1], a1y, p1a));
                p2a = fmaf(acc[mt][nt][0], a2x, fmaf(acc[mt][nt][1], a2y, p2a));
                p1b = fmaf(acc[mt][nt][2], a1x, fmaf(acc[mt][nt][3], a1y, p1b));
                p2b = fmaf(acc[mt][nt][2], a2x, fmaf(acc[mt][nt][3], a2y, p2b));
            }
            #pragma unroll
            for (int o = 1; o <= 2; o <<= 1) {
                p1a += __shfl_xor_sync(0xFFFFFFFFu, p1a, o);
                p2a += __shfl_xor_sync(0xFFFFFFFFu, p2a, o);
                p1b += __shfl_xor_sync(0xFFFFFFFFu, p1b, o);
                p2b += __shfl_xor_sync(0xFFFFFFFFu, p2b, o);
            }
            if ((lane & 3) == 0) {
                if (r0 < N_NODES) {
                    atomicAdd(&g_s1[r0], p1a);
                    atomicAdd(&g_s2[r0], p2a);
                }
                if (r0 + 8 < N_NODES) {
                    atomicAdd(&g_s1[r0 + 8], p1b);
                    atomicAdd(&g_s2[r0 + 8], p2b);
                }
            }
        }
    } else {
        #pragma unroll
        for (int mt = 0; mt < 4; mt++) {
            int r0 = bm + wm * 64 + mt * 16 + lr;
            #pragma unroll
            for (int nt = 0; nt < 4; nt++) {
                int c0 = wn * 32 + nt * 8 + lc;
                float2 br = *(const float2*)(b_res + c0);
                if (r0 < N_NODES)
                    *(float2*)(out + (size_t)r0 * D + c0) =
                        make_float2(acc[mt][nt][0] + br.x, acc[mt][nt][1] + br.y);
                if (r0 + 8 < N_NODES)
                    *(float2*)(out + (size_t)(r0 + 8) * D + c0) =
                        make_float2(acc[mt][nt][2] + br.x, acc[mt][nt][3] + br.y);
            }
        }
    }
}

// ---------------- K_agg: logit + softmax + aggregate + residual + SELU ----------------
__device__ __forceinline__ float edge_logit(unsigned pk, float s1n) {
    float l = s1n + g_s2[pk & 0xFFFFu] + g_t[pk >> 16];
    return l > 0.0f ? l : 0.2f * l;
}

__global__ __launch_bounds__(256) void k_agg(float* __restrict__ out) {
    int node = blockIdx.x * 8 + (threadIdx.x >> 5);
    if (node >= N_NODES) return;
    int lane = threadIdx.x & 31;
    int start = g_off[node];
    int cnt   = g_cnt[node];
    float s1n = g_s1[node];

    float4 acc = make_float4(0.f, 0.f, 0.f, 0.f);

    if (cnt > 0) {
        if (cnt <= 32) {
            unsigned pk = 0;
            float l = -INFINITY;
            if (lane < cnt) {
                pk = g_epack[start + lane];
                l = edge_logit(pk, s1n);
            }
            float m = l;
            #pragma unroll
            for (int o = 16; o > 0; o >>= 1)
                m = fmaxf(m, __shfl_xor_sync(0xFFFFFFFFu, m, o));
            float ev = (lane < cnt) ? __expf(l - m) : 0.0f;
            float sum = ev;
            #pragma unroll
            for (int o = 16; o > 0; o >>= 1)
                sum += __shfl_xor_sync(0xFFFFFFFFu, sum, o);
            float al = ev / (sum + 1e-16f);
            #pragma unroll 4
            for (int j = 0; j < cnt; j++) {
                float aj = __shfl_sync(0xFFFFFFFFu, al, j);
                int   sj = __shfl_sync(0xFFFFFFFFu, (int)pk, j) & 0xFFFF;
                float4 hv = *(const float4*)&g_h[(size_t)sj * D + lane * 4];
                acc.x = fmaf(hv.x, aj, acc.x);
                acc.y = fmaf(hv.y, aj, acc.y);
                acc.z = fmaf(hv.z, aj, acc.z);
                acc.w = fmaf(hv.w, aj, acc.w);
            }
        } else {
            float m = -INFINITY;
            for (int i = lane; i < cnt; i += 32)
                m = fmaxf(m, edge_logit(g_epack[start + i], s1n));
            #pragma unroll
            for (int o = 16; o > 0; o >>= 1)
                m = fmaxf(m, __shfl_xor_sync(0xFFFFFFFFu, m, o));
            float sum = 0.0f;
            for (int i = lane; i < cnt; i += 32)
                sum += __expf(edge_logit(g_epack[start + i], s1n) - m);
            #pragma unroll
            for (int o = 16; o > 0; o >>= 1)
                sum += __shfl_xor_sync(0xFFFFFFFFu, sum, o);
            float inv = 1.0f / (sum + 1e-16f);
            for (int i0 = 0; i0 < cnt; i0 += 32) {
                int i = i0 + lane;
                float al = 0.0f;
                unsigned pk = 0;
                if (i < cnt) {
                    pk = g_epack[start + i];
                    al = __expf(edge_logit(pk, s1n) - m) * inv;
                }
                int n = min(32, cnt - i0);
                #pragma unroll 4
                for (int j = 0; j < n; j++) {
                    float aj = __shfl_sync(0xFFFFFFFFu, al, j);
                    int   sj = __shfl_sync(0xFFFFFFFFu, (int)pk, j) & 0xFFFF;
                    float4 hv = *(const float4*)&g_h[(size_t)sj * D + lane * 4];
                    acc.x = fmaf(hv.x, aj, acc.x);
                    acc.y = fmaf(hv.y, aj, acc.y);
                    acc.z = fmaf(hv.z, aj, acc.z);
                    acc.w = fmaf(hv.w, aj, acc.w);
                }
            }
        }
    }

    const float scale  = 1.0507009873554805f;
    const float salpha = 1.7580993408473766f;
    float* o = out + (size_t)node * D + lane * 4;
    float4 r = *(float4*)o;
    r.x += acc.x; r.y += acc.y; r.z += acc.z; r.w += acc.w;
    r.x = r.x > 0.0f ? scale * r.x : salpha * expm1f(r.x);
    r.y = r.y > 0.0f ? scale * r.y : salpha * expm1f(r.y);
    r.z = r.z > 0.0f ? scale * r.z : salpha * expm1f(r.z);
    r.w = r.w > 0.0f ? scale * r.w : salpha * expm1f(r.w);
    *(float4*)o = r;
}

// ---------------- launch ----------------
extern "C" void kernel_launch(void* const* d_in, const int* in_sizes, int n_in,
                              void* d_out, int out_size) {
    const float* X      = (const float*)d_in[0];
    const int*   ei     = (const int*)  d_in[1];
    const int*   et     = (const int*)  d_in[2];
    const float* W      = (const float*)d_in[3];
    const float* W_r    = (const float*)d_in[4];
    const float* a      = (const float*)d_in[5];
    const float* W_res  = (const float*)d_in[6];
    const float* b_res  = (const float*)d_in[7];
    const float* rel    = (const float*)d_in[8];
    float* out = (float*)d_out;

    k_prep<<<(N_NODES + 255) / 256, 256>>>(W, W_res, W_r, a, rel);
    k_hist<<<(N_EDGES / 2 + 255) / 256, 256>>>(ei);
    k_alloc<<<(N_NODES + 1023) / 1024, 1024>>>();
    k_fill<<<(N_EDGES + 255) / 256, 256>>>(ei, et);

    dim3 ggrid((N_NODES + 127) / 128, 2);
    k_gemm_t<<<ggrid, 256>>>(X, b_res, a, out);

    k_agg<<<(N_NODES + 7) / 8, 256>>>(out);
}

// round 9
// speedup vs baseline: 3.0570x; 1.1528x over previous
#include <cuda_runtime.h>
#include <cuda_bf16.h>
#include <math.h>

#define N_NODES 50000
#define N_EDGES 600000
#define D 128
#define REL_DIM 100
#define N_REL 40

// ---------------- device scratch ----------------
__device__ __align__(32) __nv_bfloat16 g_bt[4 * D * D];  // [mat][hi/lo][n][k]
__device__ float g_h[(size_t)N_NODES * D];   // X @ W
__device__ float g_s1[N_NODES];              // h . a[:D]
__device__ float g_s2[N_NODES];              // h . a[D:2D]
__device__ float g_t[N_REL];                 // per-relation logit term
__device__ int   g_cnt[N_NODES];             // edges per dst
__device__ int   g_off[N_NODES];             // CSR segment base per dst
__device__ int   g_cur[N_NODES];             // fill cursor
__device__ int   g_ctr;                      // global bump allocator
__device__ unsigned g_epack[N_EDGES];        // dst-grouped: src | (etype<<16)

// ---------------- K_prep: zero state + split W,Wres to bf16 hi/lo + rel term ----------------
__global__ void k_prep(const float* __restrict__ W, const float* __restrict__ Wres,
                       const float* __restrict__ W_r, const float* __restrict__ a,
                       const float* __restrict__ rel_emb) {
    int i = blockIdx.x * blockDim.x + threadIdx.x;
    if (i == 0) g_ctr = 0;
    if (i < N_NODES) {
        g_cnt[i] = 0;
        g_s1[i] = 0.0f;
        g_s2[i] = 0.0f;
    }
    if (i < 2 * D * D) {
        int mat = i >> 14;              // D*D = 16384
        int rem = i & (D * D - 1);
        int k = rem >> 7, n = rem & 127;
        float w = (mat ? Wres : W)[k * D + n];
        __nv_bfloat16 hi = __float2bfloat16(w);
        __nv_bfloat16 lo = __float2bfloat16(w - __bfloat162float(hi));
        g_bt[((size_t)(mat * 2 + 0) * D + n) * D + k] = hi;
        g_bt[((size_t)(mat * 2 + 1) * D + n) * D + k] = lo;
    }
    if (blockIdx.x == 0) {
        __shared__ float v[REL_DIM];
        int t = threadIdx.x;
        if (t < REL_DIM) {
            float s = 0.0f;
            #pragma unroll 4
            for (int k = 0; k < D; k++) s = fmaf(W_r[t * D + k], a[2 * D + k], s);
            v[t] = s;
        }
        __syncthreads();
        if (t < N_REL) {
            float s = 0.0f;
            for (int j = 0; j < REL_DIM; j++) s = fmaf(rel_emb[t * REL_DIM + j], v[j], s);
            g_t[t] = s;
        }
    }
}

// ---------------- K_hist: edges per dst (4 edges / thread) ----------------
__global__ void k_hist(const int* __restrict__ ei) {
    int i = blockIdx.x * blockDim.x + threadIdx.x;
    if (i >= N_EDGES / 4) return;
    int4 d = *(const int4*)(ei + N_EDGES + 4 * i);
    atomicAdd(&g_cnt[d.x], 1);
    atomicAdd(&g_cnt[d.y], 1);
    atomicAdd(&g_cnt[d.z], 1);
    atomicAdd(&g_cnt[d.w], 1);
}

// ---------------- K_alloc: bump-allocate CSR segments (placement order irrelevant) ----------------
__global__ __launch_bounds__(1024) void k_alloc() {
    __shared__ int wsum[32];
    __shared__ int bbase;
    int i = blockIdx.x * 1024 + threadIdx.x;
    int lane = threadIdx.x & 31, wid = threadIdx.x >> 5;
    int c = (i < N_NODES) ? g_cnt[i] : 0;
    int p = c;
    #pragma unroll
    for (int o = 1; o < 32; o <<= 1) {
        int v = __shfl_up_sync(0xFFFFFFFFu, p, o);
        if (lane >= o) p += v;
    }
    if (lane == 31) wsum[wid] = p;
    __syncthreads();
    if (wid == 0) {
        int v = wsum[lane];
        int q = v;
        #pragma unroll
        for (int o = 1; o < 32; o <<= 1) {
            int u = __shfl_up_sync(0xFFFFFFFFu, q, o);
            if (lane >= o) q += u;
        }
        wsum[lane] = q - v;                 // exclusive warp base
        if (lane == 31) bbase = atomicAdd(&g_ctr, q);  // block total
    }
    __syncthreads();
    if (i < N_NODES) {
        int base = bbase + wsum[wid] + (p - c);
        g_off[i] = base;
        g_cur[i] = base;
    }
}

// ---------------- K_fill: scatter packed (src | et<<16) into CSR (2 edges / thread) ----------------
__global__ void k_fill(const int* __restrict__ ei, const int* __restrict__ et) {
    int i = blockIdx.x * blockDim.x + threadIdx.x;
    if (i >= N_EDGES / 2) return;
    int2 s = *(const int2*)(ei + 2 * i);
    int2 d = *(const int2*)(ei + N_EDGES + 2 * i);
    int2 t = *(const int2*)(et + 2 * i);
    int p0 = atomicAdd(&g_cur[d.x], 1);
    int p1 = atomicAdd(&g_cur[d.y], 1);
    g_epack[p0] = (unsigned)s.x | ((unsigned)t.x << 16);
    g_epack[p1] = (unsigned)s.y | ((unsigned)t.y << 16);
}

// ---------------- ldmatrix helpers ----------------
__device__ __forceinline__ unsigned smem_u32(const void* p) {
    return (unsigned)__cvta_generic_to_shared(p);
}
__device__ __forceinline__ void ldsm_x4(unsigned& r0, unsigned& r1, unsigned& r2,
                                        unsigned& r3, unsigned addr) {
    asm volatile("ldmatrix.sync.aligned.m8n8.x4.shared.b16 {%0,%1,%2,%3}, [%4];"
                 : "=r"(r0), "=r"(r1), "=r"(r2), "=r"(r3) : "r"(addr));
}

// ---------------- K1: tensor-core split-bf16 GEMM (ldmatrix frags) ----------------
#define ASTR 40
__global__ __launch_bounds__(256, 2) void k_gemm_t(const float* __restrict__ X,
                                                   const float* __restrict__ b_res,
                                                   const float* __restrict__ a,
                                                   float* __restrict__ out) {
    __shared__ __align__(16) __nv_bfloat16 AsH[128 * ASTR];
    __shared__ __align__(16) __nv_bfloat16 AsL[128 * ASTR];
    __shared__ __align__(16) __nv_bfloat16 BsH[128 * ASTR];
    __shared__ __align__(16) __nv_bfloat16 BsL[128 * ASTR];
    int tid = threadIdx.x;
    int bm = blockIdx.x * 128;
    int y = blockIdx.y;
    const __nv_bfloat16* BtH = g_bt + (size_t)(y * 2 + 0) * D * D;
    const __nv_bfloat16* BtL = g_bt + (size_t)(y * 2 + 1) * D * D;
    int w = tid >> 5, lane = tid & 31;
    int wm = w & 1, wn = w >> 1;
    int lr = lane >> 2, lc = (lane & 3) * 2;

    float acc[4][4][4];
    #pragma unroll
    for (int i = 0; i < 4; i++)
        #pragma unroll
        for (int j = 0; j < 4; j++)
            #pragma unroll
            for (int q = 0; q < 4; q++) acc[i][j][q] = 0.0f;

    int lm = tid & 127;
    int ls = (tid >> 7) * 16;
    int gm = bm + lm;
    bool valid = gm < N_NODES;

    int arow = lane & 15;
    int acol = (lane >> 4) * 8;
    int nrow = (lane & 7) + ((lane >> 4) & 1) * 8;
    int kcol = ((lane >> 3) & 1) * 8;

    for (int kc = 0; kc < D; kc += 32) {
        float f[16];
        #pragma unroll
        for (int i = 0; i < 4; i++) {
            float4 v = make_float4(0.f, 0.f, 0.f, 0.f);
            if (valid) v = *(const float4*)(X + (size_t)gm * D + kc + ls + i * 4);
            f[i * 4 + 0] = v.x; f[i * 4 + 1] = v.y; f[i * 4 + 2] = v.z; f[i * 4 + 3] = v.w;
        }
        unsigned hp[8], lp[8];
        #pragma unroll
        for (int j = 0; j < 8; j++) {
            __nv_bfloat16 h0 = __float2bfloat16(f[2 * j]);
            __nv_bfloat16 h1 = __float2bfloat16(f[2 * j + 1]);
            __nv_bfloat16 e0 = __float2bfloat16(f[2 * j] - __bfloat162float(h0));
            __nv_bfloat16 e1 = __float2bfloat16(f[2 * j + 1] - __bfloat162float(h1));
            hp[j] = ((unsigned)__bfloat16_as_ushort(h1) << 16) | __bfloat16_as_ushort(h0);
            lp[j] = ((unsigned)__bfloat16_as_ushort(e1) << 16) | __bfloat16_as_ushort(e0);
        }
        __nv_bfloat16* ah = &AsH[lm * ASTR + ls];
        __nv_bfloat16* al = &AsL[lm * ASTR + ls];
        #pragma unroll
        for (int j = 0; j < 4; j++) {
            ((uint2*)ah)[j] = make_uint2(hp[2 * j], hp[2 * j + 1]);
            ((uint2*)al)[j] = make_uint2(lp[2 * j], lp[2 * j + 1]);
        }
        {
            const uint4* qh = (const uint4*)(BtH + (size_t)lm * D + kc + ls);
            const uint4* ql = (const uint4*)(BtL + (size_t)lm * D + kc + ls);
            uint4 h0 = qh[0], h1 = qh[1], l0 = ql[0], l1 = ql[1];
            __nv_bfloat16* bh = &BsH[lm * ASTR + ls];
            __nv_bfloat16* bl = &BsL[lm * ASTR + ls];
            ((uint2*)bh)[0] = make_uint2(h0.x, h0.y);
            ((uint2*)bh)[1] = make_uint2(h0.z, h0.w);
            ((uint2*)bh)[2] = make_uint2(h1.x, h1.y);
            ((uint2*)bh)[3] = make_uint2(h1.z, h1.w);
            ((uint2*)bl)[0] = make_uint2(l0.x, l0.y);
            ((uint2*)bl)[1] = make_uint2(l0.z, l0.w);
            ((uint2*)bl)[2] = make_uint2(l1.x, l1.y);
            ((uint2*)bl)[3] = make_uint2(l1.z, l1.w);
        }
        __syncthreads();

        #pragma unroll
        for (int ks = 0; ks < 32; ks += 16) {
            unsigned afH[4][4], bfH[4][2], bfL[4][2];
            #pragma unroll
            for (int mt = 0; mt < 4; mt++) {
                unsigned ad = smem_u32(&AsH[(wm * 64 + mt * 16 + arow) * ASTR + ks + acol]);
                ldsm_x4(afH[mt][0], afH[mt][1], afH[mt][2], afH[mt][3], ad);
            }
            #pragma unroll
            for (int p = 0; p < 2; p++) {
                unsigned bdh = smem_u32(&BsH[(wn * 32 + p * 16 + nrow) * ASTR + ks + kcol]);
                ldsm_x4(bfH[2 * p][0], bfH[2 * p][1], bfH[2 * p + 1][0], bfH[2 * p + 1][1], bdh);
                unsigned bdl = smem_u32(&BsL[(wn * 32 + p * 16 + nrow) * ASTR + ks + kcol]);
                ldsm_x4(bfL[2 * p][0], bfL[2 * p][1], bfL[2 * p + 1][0], bfL[2 * p + 1][1], bdl);
            }
            #pragma unroll
            for (int mt = 0; mt < 4; mt++)
                #pragma unroll
                for (int nt = 0; nt < 4; nt++) {
                    asm volatile(
                        "mma.sync.aligned.m16n8k16.row.col.f32.bf16.bf16.f32 "
                        "{%0,%1,%2,%3}, {%4,%5,%6,%7}, {%8,%9}, {%0,%1,%2,%3};"
                        : "+f"(acc[mt][nt][0]), "+f"(acc[mt][nt][1]),
                          "+f"(acc[mt][nt][2]), "+f"(acc[mt][nt][3])
                        : "r"(afH[mt][0]), "r"(afH[mt][1]), "r"(afH[mt][2]), "r"(afH[mt][3]),
                          "r"(bfH[nt][0]), "r"(bfH[nt][1]));
                    asm volatile(
                        "mma.sync.aligned.m16n8k16.row.col.f32.bf16.bf16.f32 "
                        "{%0,%1,%2,%3}, {%4,%5,%6,%7}, {%8,%9}, {%0,%1,%2,%3};"
                        : "+f"(acc[mt][nt][0]), "+f"(acc[mt][nt][1]),
                          "+f"(acc[mt][nt][2]), "+f"(acc[mt][nt][3])
                        : "r"(afH[mt][0]), "r"(afH[mt][1]), "r"(afH[mt][2]), "r"(afH[mt][3]),
                          "r"(bfL[nt][0]), "r"(bfL[nt][1]));
                }
            #pragma unroll
            for (int mt = 0; mt < 4; mt++) {
                unsigned a0, a1, a2, a3;
                unsigned ad = smem_u32(&AsL[(wm * 64 + mt * 16 + arow) * ASTR + ks + acol]);
                ldsm_x4(a0, a1, a2, a3, ad);
                #pragma unroll
                for (int nt = 0; nt < 4; nt++)
                    asm volatile(
                        "mma.sync.aligned.m16n8k16.row.col.f32.bf16.bf16.f32 "
                        "{%0,%1,%2,%3}, {%4,%5,%6,%7}, {%8,%9}, {%0,%1,%2,%3};"
                        : "+f"(acc[mt][nt][0]), "+f"(acc[mt][nt][1]),
                          "+f"(acc[mt][nt][2]), "+f"(acc[mt][nt][3])
                        : "r"(a0), "r"(a1), "r"(a2), "r"(a3),
                          "r"(bfH[nt][0]), "r"(bfH[nt][1]));
            }
        }
        __syncthreads();
    }

    if (y == 0) {
        #pragma unroll
        for (int mt = 0; mt < 4; mt++) {
            int r0 = bm + wm * 64 + mt * 16 + lr;
            float p1a = 0.f, p2a = 0.f, p1b = 0.f, p2b = 0.f;
            #pragma unroll
            for (int nt = 0; nt < 4; nt++) {
                int c0 = wn * 32 + nt * 8 + lc;
                float a1x = a[c0], a1y = a[c0 + 1];
                float a2x = a[D + c0], a2y = a[D + c0 + 1];
                if (r0 < N_NODES)
                    *(float2*)&g_h[(size_t)r0 * D + c0] =
                        make_float2(acc[mt][nt][0], acc[mt][nt][1]);
                if (r0 + 8 < N_NODES)
                    *(float2*)&g_h[(size_t)(r0 + 8) * D + c0] =
                        make_float2(acc[mt][nt][2], acc[mt][nt][3]);
                p1a = fmaf(acc[mt][nt][0], a1x, fmaf(acc[mt][nt][1], a1y, p1a));
                p2a = fmaf(acc[mt][nt][0], a2x, fmaf(acc[mt][nt][1], a2y, p2a));
                p1b = fmaf(acc[mt][nt][2], a1x, fmaf(acc[mt][nt][3], a1y, p1b));
                p2b = fmaf(acc[mt][nt][2], a2x, fmaf(acc[mt][nt][3], a2y, p2b));
            }
            #pragma unroll
            for (int o = 1; o <= 2; o <<= 1) {
                p1a += __shfl_xor_sync(0xFFFFFFFFu, p1a, o);
                p2a += __shfl_xor_sync(0xFFFFFFFFu, p2a, o);
                p1b += __shfl_xor_sync(0xFFFFFFFFu, p1b, o);
                p2b += __shfl_xor_sync(0xFFFFFFFFu, p2b, o);
            }
            if ((lane & 3) == 0) {
                if (r0 < N_NODES) {
                    atomicAdd(&g_s1[r0], p1a);
                    atomicAdd(&g_s2[r0], p2a);
                }
                if (r0 + 8 < N_NODES) {
                    atomicAdd(&g_s1[r0 + 8], p1b);
                    atomicAdd(&g_s2[r0 + 8], p2b);
                }
            }
        }
    } else {
        #pragma unroll
        for (int mt = 0; mt < 4; mt++) {
            int r0 = bm + wm * 64 + mt * 16 + lr;
            #pragma unroll
            for (int nt = 0; nt < 4; nt++) {
                int c0 = wn * 32 + nt * 8 + lc;
                float2 br = *(const float2*)(b_res + c0);
                if (r0 < N_NODES)
                    *(float2*)(out + (size_t)r0 * D + c0) =
                        make_float2(acc[mt][nt][0] + br.x, acc[mt][nt][1] + br.y);
                if (r0 + 8 < N_NODES)
                    *(float2*)(out + (size_t)(r0 + 8) * D + c0) =
                        make_float2(acc[mt][nt][2] + br.x, acc[mt][nt][3] + br.y);
            }
        }
    }
}

// ---------------- K_agg: logit + softmax + aggregate + residual + SELU ----------------
__device__ __forceinline__ float edge_logit(unsigned pk, float s1n) {
    float l = s1n + g_s2[pk & 0xFFFFu] + g_t[pk >> 16];
    return l > 0.0f ? l : 0.2f * l;
}

__global__ __launch_bounds__(256) void k_agg(float* __restrict__ out) {
    int node = blockIdx.x * 8 + (threadIdx.x >> 5);
    if (node >= N_NODES) return;
    int lane = threadIdx.x & 31;
    int start = g_off[node];
    int cnt   = g_cnt[node];
    float s1n = g_s1[node];

    float4 acc = make_float4(0.f, 0.f, 0.f, 0.f);

    if (cnt > 0) {
        if (cnt <= 32) {
            unsigned pk = 0;
            float l = -INFINITY;
            if (lane < cnt) {
                pk = g_epack[start + lane];
                l = edge_logit(pk, s1n);
            }
            float m = l;
            #pragma unroll
            for (int o = 16; o > 0; o >>= 1)
                m = fmaxf(m, __shfl_xor_sync(0xFFFFFFFFu, m, o));
            float ev = (lane < cnt) ? __expf(l - m) : 0.0f;
            float sum = ev;
            #pragma unroll
            for (int o = 16; o > 0; o >>= 1)
                sum += __shfl_xor_sync(0xFFFFFFFFu, sum, o);
            float al = ev / (sum + 1e-16f);
            #pragma unroll 4
            for (int j = 0; j < cnt; j++) {
                float aj = __shfl_sync(0xFFFFFFFFu, al, j);
                int   sj = __shfl_sync(0xFFFFFFFFu, (int)pk, j) & 0xFFFF;
                float4 hv = *(const float4*)&g_h[(size_t)sj * D + lane * 4];
                acc.x = fmaf(hv.x, aj, acc.x);
                acc.y = fmaf(hv.y, aj, acc.y);
                acc.z = fmaf(hv.z, aj, acc.z);
                acc.w = fmaf(hv.w, aj, acc.w);
            }
        } else {
            float m = -INFINITY;
            for (int i = lane; i < cnt; i += 32)
                m = fmaxf(m, edge_logit(g_epack[start + i], s1n));
            #pragma unroll
            for (int o = 16; o > 0; o >>= 1)
                m = fmaxf(m, __shfl_xor_sync(0xFFFFFFFFu, m, o));
            float sum = 0.0f;
            for (int i = lane; i < cnt; i += 32)
                sum += __expf(edge_logit(g_epack[start + i], s1n) - m);
            #pragma unroll
            for (int o = 16; o > 0; o >>= 1)
                sum += __shfl_xor_sync(0xFFFFFFFFu, sum, o);
            float inv = 1.0f / (sum + 1e-16f);
            for (int i0 = 0; i0 < cnt; i0 += 32) {
                int i = i0 + lane;
                float al = 0.0f;
                unsigned pk = 0;
                if (i < cnt) {
                    pk = g_epack[start + i];
                    al = __expf(edge_logit(pk, s1n) - m) * inv;
                }
                int n = min(32, cnt - i0);
                #pragma unroll 4
                for (int j = 0; j < n; j++) {
                    float aj = __shfl_sync(0xFFFFFFFFu, al, j);
                    int   sj = __shfl_sync(0xFFFFFFFFu, (int)pk, j) & 0xFFFF;
                    float4 hv = *(const float4*)&g_h[(size_t)sj * D + lane * 4];
                    acc.x = fmaf(hv.x, aj, acc.x);
                    acc.y = fmaf(hv.y, aj, acc.y);
                    acc.z = fmaf(hv.z, aj, acc.z);
                    acc.w = fmaf(hv.w, aj, acc.w);
                }
            }
        }
    }

    const float scale  = 1.0507009873554805f;
    const float salpha = 1.7580993408473766f;
    float* o = out + (size_t)node * D + lane * 4;
    float4 r = *(float4*)o;
    r.x += acc.x; r.y += acc.y; r.z += acc.z; r.w += acc.w;
    r.x = r.x > 0.0f ? scale * r.x : salpha * expm1f(r.x);
    r.y = r.y > 0.0f ? scale * r.y : salpha * expm1f(r.y);
    r.z = r.z > 0.0f ? scale * r.z : salpha * expm1f(r.z);
    r.w = r.w > 0.0f ? scale * r.w : salpha * expm1f(r.w);
    *(float4*)o = r;
}

// ---------------- launch (fork edge-prep onto a side stream, overlap with GEMM) ----------------
extern "C" void kernel_launch(void* const* d_in, const int* in_sizes, int n_in,
                              void* d_out, int out_size) {
    const float* X      = (const float*)d_in[0];
    const int*   ei     = (const int*)  d_in[1];
    const int*   et     = (const int*)  d_in[2];
    const float* W      = (const float*)d_in[3];
    const float* W_r    = (const float*)d_in[4];
    const float* a      = (const float*)d_in[5];
    const float* W_res  = (const float*)d_in[6];
    const float* b_res  = (const float*)d_in[7];
    const float* rel    = (const float*)d_in[8];
    float* out = (float*)d_out;

    // created once on the (uncaptured) correctness call; reused by graph capture
    static cudaStream_t s2 = nullptr;
    static cudaEvent_t evF = nullptr, evJ = nullptr;
    if (s2 == nullptr) {
        cudaStreamCreateWithFlags(&s2, cudaStreamNonBlocking);
        cudaEventCreateWithFlags(&evF, cudaEventDisableTiming);
        cudaEventCreateWithFlags(&evJ, cudaEventDisableTiming);
    }

    k_prep<<<(N_NODES + 255) / 256, 256>>>(W, W_res, W_r, a, rel);

    // fork: edge-prep chain on s2, GEMM on stream 0
    cudaEventRecord(evF, 0);
    cudaStreamWaitEvent(s2, evF, 0);
    k_hist<<<(N_EDGES / 4 + 255) / 256, 256, 0, s2>>>(ei);
    k_alloc<<<(N_NODES + 1023) / 1024, 1024, 0, s2>>>();
    k_fill<<<(N_EDGES / 2 + 255) / 256, 256, 0, s2>>>(ei, et);
    cudaEventRecord(evJ, s2);

    dim3 ggrid((N_NODES + 127) / 128, 2);
    k_gemm_t<<<ggrid, 256>>>(X, b_res, a, out);

    // join, then aggregate
    cudaStreamWaitEvent(0, evJ, 0);
    k_agg<<<(N_NODES + 7) / 8, 256>>>(out);
}

// round 10
// speedup vs baseline: 3.1366x; 1.0260x over previous
#include <cuda_runtime.h>
#include <cuda_bf16.h>
#include <math.h>

#define N_NODES 50000
#define N_EDGES 600000
#define D 128
#define REL_DIM 100
#define N_REL 40

// ---------------- device scratch ----------------
__device__ __align__(32) __nv_bfloat16 g_bt[4 * D * D];  // [mat][hi/lo][n][k]
__device__ float g_h[(size_t)N_NODES * D];   // X @ W
__device__ float g_s1[N_NODES];              // h . a[:D]
__device__ float g_s2[N_NODES];              // h . a[D:2D]
__device__ float g_t[N_REL];                 // per-relation logit term
__device__ int   g_cnt[N_NODES];             // edges per dst
__device__ int   g_off[N_NODES];             // CSR segment base per dst
__device__ int   g_cur[N_NODES];             // fill cursor
__device__ int   g_ctr;                      // global bump allocator
__device__ unsigned g_epack[N_EDGES];        // dst-grouped: src | (etype<<16)

// ---------------- K_prep: zero state + split W,Wres to bf16 hi/lo + rel term ----------------
__global__ void k_prep(const float* __restrict__ W, const float* __restrict__ Wres,
                       const float* __restrict__ W_r, const float* __restrict__ a,
                       const float* __restrict__ rel_emb) {
    int i = blockIdx.x * blockDim.x + threadIdx.x;
    if (i == 0) g_ctr = 0;
    if (i < N_NODES) {
        g_cnt[i] = 0;
        g_s1[i] = 0.0f;
        g_s2[i] = 0.0f;
    }
    if (i < 2 * D * D) {
        int mat = i >> 14;              // D*D = 16384
        int rem = i & (D * D - 1);
        int k = rem >> 7, n = rem & 127;
        float w = (mat ? Wres : W)[k * D + n];
        __nv_bfloat16 hi = __float2bfloat16(w);
        __nv_bfloat16 lo = __float2bfloat16(w - __bfloat162float(hi));
        g_bt[((size_t)(mat * 2 + 0) * D + n) * D + k] = hi;
        g_bt[((size_t)(mat * 2 + 1) * D + n) * D + k] = lo;
    }
    if (blockIdx.x == 0) {
        __shared__ float v[REL_DIM];
        int t = threadIdx.x;
        if (t < REL_DIM) {
            float s = 0.0f;
            #pragma unroll 4
            for (int k = 0; k < D; k++) s = fmaf(W_r[t * D + k], a[2 * D + k], s);
            v[t] = s;
        }
        __syncthreads();
        if (t < N_REL) {
            float s = 0.0f;
            for (int j = 0; j < REL_DIM; j++) s = fmaf(rel_emb[t * REL_DIM + j], v[j], s);
            g_t[t] = s;
        }
    }
}

// ---------------- K_hist: edges per dst (4 edges / thread) ----------------
__global__ void k_hist(const int* __restrict__ ei) {
    int i = blockIdx.x * blockDim.x + threadIdx.x;
    if (i >= N_EDGES / 4) return;
    int4 d = *(const int4*)(ei + N_EDGES + 4 * i);
    atomicAdd(&g_cnt[d.x], 1);
    atomicAdd(&g_cnt[d.y], 1);
    atomicAdd(&g_cnt[d.z], 1);
    atomicAdd(&g_cnt[d.w], 1);
}

// ---------------- K_alloc: bump-allocate CSR segments ----------------
__global__ __launch_bounds__(1024) void k_alloc() {
    __shared__ int wsum[32];
    __shared__ int bbase;
    int i = blockIdx.x * 1024 + threadIdx.x;
    int lane = threadIdx.x & 31, wid = threadIdx.x >> 5;
    int c = (i < N_NODES) ? g_cnt[i] : 0;
    int p = c;
    #pragma unroll
    for (int o = 1; o < 32; o <<= 1) {
        int v = __shfl_up_sync(0xFFFFFFFFu, p, o);
        if (lane >= o) p += v;
    }
    if (lane == 31) wsum[wid] = p;
    __syncthreads();
    if (wid == 0) {
        int v = wsum[lane];
        int q = v;
        #pragma unroll
        for (int o = 1; o < 32; o <<= 1) {
            int u = __shfl_up_sync(0xFFFFFFFFu, q, o);
            if (lane >= o) q += u;
        }
        wsum[lane] = q - v;
        if (lane == 31) bbase = atomicAdd(&g_ctr, q);
    }
    __syncthreads();
    if (i < N_NODES) {
        int base = bbase + wsum[wid] + (p - c);
        g_off[i] = base;
        g_cur[i] = base;
    }
}

// ---------------- K_fill: scatter packed (src | et<<16) into CSR (2 edges / thread) ----------------
__global__ void k_fill(const int* __restrict__ ei, const int* __restrict__ et) {
    int i = blockIdx.x * blockDim.x + threadIdx.x;
    if (i >= N_EDGES / 2) return;
    int2 s = *(const int2*)(ei + 2 * i);
    int2 d = *(const int2*)(ei + N_EDGES + 2 * i);
    int2 t = *(const int2*)(et + 2 * i);
    int p0 = atomicAdd(&g_cur[d.x], 1);
    int p1 = atomicAdd(&g_cur[d.y], 1);
    g_epack[p0] = (unsigned)s.x | ((unsigned)t.x << 16);
    g_epack[p1] = (unsigned)s.y | ((unsigned)t.y << 16);
}

// ---------------- ldmatrix helpers ----------------
__device__ __forceinline__ unsigned smem_u32(const void* p) {
    return (unsigned)__cvta_generic_to_shared(p);
}
__device__ __forceinline__ void ldsm_x4(unsigned& r0, unsigned& r1, unsigned& r2,
                                        unsigned& r3, unsigned addr) {
    asm volatile("ldmatrix.sync.aligned.m8n8.x4.shared.b16 {%0,%1,%2,%3}, [%4];"
                 : "=r"(r0), "=r"(r1), "=r"(r2), "=r"(r3) : "r"(addr));
}

// ---------------- K1: tensor-core split-bf16 GEMM (ldmatrix frags) ----------------
#define ASTR 40
__global__ __launch_bounds__(256, 2) void k_gemm_t(const float* __restrict__ X,
                                                   const float* __restrict__ b_res,
                                                   const float* __restrict__ a,
                                                   float* __restrict__ out) {
    __shared__ __align__(16) __nv_bfloat16 AsH[128 * ASTR];
    __shared__ __align__(16) __nv_bfloat16 AsL[128 * ASTR];
    __shared__ __align__(16) __nv_bfloat16 BsH[128 * ASTR];
    __shared__ __align__(16) __nv_bfloat16 BsL[128 * ASTR];
    int tid = threadIdx.x;
    int bm = blockIdx.x * 128;
    int y = blockIdx.y;
    const __nv_bfloat16* BtH = g_bt + (size_t)(y * 2 + 0) * D * D;
    const __nv_bfloat16* BtL = g_bt + (size_t)(y * 2 + 1) * D * D;
    int w = tid >> 5, lane = tid & 31;
    int wm = w & 1, wn = w >> 1;
    int lr = lane >> 2, lc = (lane & 3) * 2;

    float acc[4][4][4];
    #pragma unroll
    for (int i = 0; i < 4; i++)
        #pragma unroll
        for (int j = 0; j < 4; j++)
            #pragma unroll
            for (int q = 0; q < 4; q++) acc[i][j][q] = 0.0f;

    int lm = tid & 127;
    int ls = (tid >> 7) * 16;
    int gm = bm + lm;
    bool valid = gm < N_NODES;

    int arow = lane & 15;
    int acol = (lane >> 4) * 8;
    int nrow = (lane & 7) + ((lane >> 4) & 1) * 8;
    int kcol = ((lane >> 3) & 1) * 8;

    for (int kc = 0; kc < D; kc += 32) {
        float f[16];
        #pragma unroll
        for (int i = 0; i < 4; i++) {
            float4 v = make_float4(0.f, 0.f, 0.f, 0.f);
            if (valid) v = *(const float4*)(X + (size_t)gm * D + kc + ls + i * 4);
            f[i * 4 + 0] = v.x; f[i * 4 + 1] = v.y; f[i * 4 + 2] = v.z; f[i * 4 + 3] = v.w;
        }
        unsigned hp[8], lp[8];
        #pragma unroll
        for (int j = 0; j < 8; j++) {
            __nv_bfloat16 h0 = __float2bfloat16(f[2 * j]);
            __nv_bfloat16 h1 = __float2bfloat16(f[2 * j + 1]);
            __nv_bfloat16 e0 = __float2bfloat16(f[2 * j] - __bfloat162float(h0));
            __nv_bfloat16 e1 = __float2bfloat16(f[2 * j + 1] - __bfloat162float(h1));
            hp[j] = ((unsigned)__bfloat16_as_ushort(h1) << 16) | __bfloat16_as_ushort(h0);
            lp[j] = ((unsigned)__bfloat16_as_ushort(e1) << 16) | __bfloat16_as_ushort(e0);
        }
        __nv_bfloat16* ah = &AsH[lm * ASTR + ls];
        __nv_bfloat16* al = &AsL[lm * ASTR + ls];
        #pragma unroll
        for (int j = 0; j < 4; j++) {
            ((uint2*)ah)[j] = make_uint2(hp[2 * j], hp[2 * j + 1]);
            ((uint2*)al)[j] = make_uint2(lp[2 * j], lp[2 * j + 1]);
        }
        {
            const uint4* qh = (const uint4*)(BtH + (size_t)lm * D + kc + ls);
            const uint4* ql = (const uint4*)(BtL + (size_t)lm * D + kc + ls);
            uint4 h0 = qh[0], h1 = qh[1], l0 = ql[0], l1 = ql[1];
            __nv_bfloat16* bh = &BsH[lm * ASTR + ls];
            __nv_bfloat16* bl = &BsL[lm * ASTR + ls];
            ((uint2*)bh)[0] = make_uint2(h0.x, h0.y);
            ((uint2*)bh)[1] = make_uint2(h0.z, h0.w);
            ((uint2*)bh)[2] = make_uint2(h1.x, h1.y);
            ((uint2*)bh)[3] = make_uint2(h1.z, h1.w);
            ((uint2*)bl)[0] = make_uint2(l0.x, l0.y);
            ((uint2*)bl)[1] = make_uint2(l0.z, l0.w);
            ((uint2*)bl)[2] = make_uint2(l1.x, l1.y);
            ((uint2*)bl)[3] = make_uint2(l1.z, l1.w);
        }
        __syncthreads();

        #pragma unroll
        for (int ks = 0; ks < 32; ks += 16) {
            unsigned afH[4][4], bfH[4][2], bfL[4][2];
            #pragma unroll
            for (int mt = 0; mt < 4; mt++) {
                unsigned ad = smem_u32(&AsH[(wm * 64 + mt * 16 + arow) * ASTR + ks + acol]);
                ldsm_x4(afH[mt][0], afH[mt][1], afH[mt][2], afH[mt][3], ad);
            }
            #pragma unroll
            for (int p = 0; p < 2; p++) {
                unsigned bdh = smem_u32(&BsH[(wn * 32 + p * 16 + nrow) * ASTR + ks + kcol]);
                ldsm_x4(bfH[2 * p][0], bfH[2 * p][1], bfH[2 * p + 1][0], bfH[2 * p + 1][1], bdh);
                unsigned bdl = smem_u32(&BsL[(wn * 32 + p * 16 + nrow) * ASTR + ks + kcol]);
                ldsm_x4(bfL[2 * p][0], bfL[2 * p][1], bfL[2 * p + 1][0], bfL[2 * p + 1][1], bdl);
            }
            #pragma unroll
            for (int mt = 0; mt < 4; mt++)
                #pragma unroll
                for (int nt = 0; nt < 4; nt++) {
                    asm volatile(
                        "mma.sync.aligned.m16n8k16.row.col.f32.bf16.bf16.f32 "
                        "{%0,%1,%2,%3}, {%4,%5,%6,%7}, {%8,%9}, {%0,%1,%2,%3};"
                        : "+f"(acc[mt][nt][0]), "+f"(acc[mt][nt][1]),
                          "+f"(acc[mt][nt][2]), "+f"(acc[mt][nt][3])
                        : "r"(afH[mt][0]), "r"(afH[mt][1]), "r"(afH[mt][2]), "r"(afH[mt][3]),
                          "r"(bfH[nt][0]), "r"(bfH[nt][1]));
                    asm volatile(
                        "mma.sync.aligned.m16n8k16.row.col.f32.bf16.bf16.f32 "
                        "{%0,%1,%2,%3}, {%4,%5,%6,%7}, {%8,%9}, {%0,%1,%2,%3};"
                        : "+f"(acc[mt][nt][0]), "+f"(acc[mt][nt][1]),
                          "+f"(acc[mt][nt][2]), "+f"(acc[mt][nt][3])
                        : "r"(afH[mt][0]), "r"(afH[mt][1]), "r"(afH[mt][2]), "r"(afH[mt][3]),
                          "r"(bfL[nt][0]), "r"(bfL[nt][1]));
                }
            #pragma unroll
            for (int mt = 0; mt < 4; mt++) {
                unsigned a0, a1, a2, a3;
                unsigned ad = smem_u32(&AsL[(wm * 64 + mt * 16 + arow) * ASTR + ks + acol]);
                ldsm_x4(a0, a1, a2, a3, ad);
                #pragma unroll
                for (int nt = 0; nt < 4; nt++)
                    asm volatile(
                        "mma.sync.aligned.m16n8k16.row.col.f32.bf16.bf16.f32 "
                        "{%0,%1,%2,%3}, {%4,%5,%6,%7}, {%8,%9}, {%0,%1,%2,%3};"
                        : "+f"(acc[mt][nt][0]), "+f"(acc[mt][nt][1]),
                          "+f"(acc[mt][nt][2]), "+f"(acc[mt][nt][3])
                        : "r"(a0), "r"(a1), "r"(a2), "r"(a3),
                          "r"(bfH[nt][0]), "r"(bfH[nt][1]));
            }
        }
        __syncthreads();
    }

    if (y == 0) {
        #pragma unroll
        for (int mt = 0; mt < 4; mt++) {
            int r0 = bm + wm * 64 + mt * 16 + lr;
            float p1a = 0.f, p2a = 0.f, p1b = 0.f, p2b = 0.f;
            #pragma unroll
            for (int nt = 0; nt < 4; nt++) {
                int c0 = wn * 32 + nt * 8 + lc;
                float a1x = a[c0], a1y = a[c0 + 1];
                float a2x = a[D + c0], a2y = a[D + c0 + 1];
                if (r0 < N_NODES)
                    *(float2*)&g_h[(size_t)r0 * D + c0] =
                        make_float2(acc[mt][nt][0], acc[mt][nt][1]);
                if (r0 + 8 < N_NODES)
                    *(float2*)&g_h[(size_t)(r0 + 8) * D + c0] =
                        make_float2(acc[mt][nt][2], acc[mt][nt][3]);
                p1a = fmaf(acc[mt][nt][0], a1x, fmaf(acc[mt][nt][1], a1y, p1a));
                p2a = fmaf(acc[mt][nt][0], a2x, fmaf(acc[mt][nt][1], a2y, p2a));
                p1b = fmaf(acc[mt][nt][2], a1x, fmaf(acc[mt][nt][3], a1y, p1b));
                p2b = fmaf(acc[mt][nt][2], a2x, fmaf(acc[mt][nt][3], a2y, p2b));
            }
            #pragma unroll
            for (int o = 1; o <= 2; o <<= 1) {
                p1a += __shfl_xor_sync(0xFFFFFFFFu, p1a, o);
                p2a += __shfl_xor_sync(0xFFFFFFFFu, p2a, o);
                p1b += __shfl_xor_sync(0xFFFFFFFFu, p1b, o);
                p2b += __shfl_xor_sync(0xFFFFFFFFu, p2b, o);
            }
            if ((lane & 3) == 0) {
                if (r0 < N_NODES) {
                    atomicAdd(&g_s1[r0], p1a);
                    atomicAdd(&g_s2[r0], p2a);
                }
                if (r0 + 8 < N_NODES) {
                    atomicAdd(&g_s1[r0 + 8], p1b);
                    atomicAdd(&g_s2[r0 + 8], p2b);
                }
            }
        }
    } else {
        #pragma unroll
        for (int mt = 0; mt < 4; mt++) {
            int r0 = bm + wm * 64 + mt * 16 + lr;
            #pragma unroll
            for (int nt = 0; nt < 4; nt++) {
                int c0 = wn * 32 + nt * 8 + lc;
                float2 br = *(const float2*)(b_res + c0);
                if (r0 < N_NODES)
                    *(float2*)(out + (size_t)r0 * D + c0) =
                        make_float2(acc[mt][nt][0] + br.x, acc[mt][nt][1] + br.y);
                if (r0 + 8 < N_NODES)
                    *(float2*)(out + (size_t)(r0 + 8) * D + c0) =
                        make_float2(acc[mt][nt][2] + br.x, acc[mt][nt][3] + br.y);
            }
        }
    }
}

// ---------------- K_agg: logit + softmax + aggregate + residual + SELU ----------------
__device__ __forceinline__ float edge_logit(unsigned pk, float s1n) {
    float l = s1n + g_s2[pk & 0xFFFFu] + g_t[pk >> 16];
    return l > 0.0f ? l : 0.2f * l;
}

// SELU via MUFU-based __expf: scale*x for x>0, salpha*exp(x)-salpha otherwise.
__device__ __forceinline__ float selu_f(float x) {
    const float scale  = 1.0507009873554805f;
    const float salpha = 1.7580993408473766f;
    return x > 0.0f ? scale * x : fmaf(salpha, __expf(x), -salpha);
}

__global__ __launch_bounds__(256) void k_agg(float* __restrict__ out) {
    int node = blockIdx.x * 8 + (threadIdx.x >> 5);
    if (node >= N_NODES) return;
    int lane = threadIdx.x & 31;
    int start = g_off[node];
    int cnt   = g_cnt[node];
    float s1n = g_s1[node];

    float4 acc = make_float4(0.f, 0.f, 0.f, 0.f);

    if (cnt > 0) {
        if (cnt <= 32) {
            unsigned pk = 0;
            float l = -INFINITY;
            if (lane < cnt) {
                pk = g_epack[start + lane];
                l = edge_logit(pk, s1n);
            }
            float m = l;
            #pragma unroll
            for (int o = 16; o > 0; o >>= 1)
                m = fmaxf(m, __shfl_xor_sync(0xFFFFFFFFu, m, o));
            float ev = (lane < cnt) ? __expf(l - m) : 0.0f;
            float sum = ev;
            #pragma unroll
            for (int o = 16; o > 0; o >>= 1)
                sum += __shfl_xor_sync(0xFFFFFFFFu, sum, o);
            float al = ev * __fdividef(1.0f, sum + 1e-16f);
            #pragma unroll 4
            for (int j = 0; j < cnt; j++) {
                float aj = __shfl_sync(0xFFFFFFFFu, al, j);
                int   sj = __shfl_sync(0xFFFFFFFFu, (int)pk, j) & 0xFFFF;
                float4 hv = *(const float4*)&g_h[(size_t)sj * D + lane * 4];
                acc.x = fmaf(hv.x, aj, acc.x);
                acc.y = fmaf(hv.y, aj, acc.y);
                acc.z = fmaf(hv.z, aj, acc.z);
                acc.w = fmaf(hv.w, aj, acc.w);
            }
        } else {
            float m = -INFINITY;
            for (int i = lane; i < cnt; i += 32)
                m = fmaxf(m, edge_logit(g_epack[start + i], s1n));
            #pragma unroll
            for (int o = 16; o > 0; o >>= 1)
                m = fmaxf(m, __shfl_xor_sync(0xFFFFFFFFu, m, o));
            float sum = 0.0f;
            for (int i = lane; i < cnt; i += 32)
                sum += __expf(edge_logit(g_epack[start + i], s1n) - m);
            #pragma unroll
            for (int o = 16; o > 0; o >>= 1)
                sum += __shfl_xor_sync(0xFFFFFFFFu, sum, o);
            float inv = __fdividef(1.0f, sum + 1e-16f);
            for (int i0 = 0; i0 < cnt; i0 += 32) {
                int i = i0 + lane;
                float al = 0.0f;
                unsigned pk = 0;
                if (i < cnt) {
                    pk = g_epack[start + i];
                    al = __expf(edge_logit(pk, s1n) - m) * inv;
                }
                int n = min(32, cnt - i0);
                #pragma unroll 4
                for (int j = 0; j < n; j++) {
                    float aj = __shfl_sync(0xFFFFFFFFu, al, j);
                    int   sj = __shfl_sync(0xFFFFFFFFu, (int)pk, j) & 0xFFFF;
                    float4 hv = *(const float4*)&g_h[(size_t)sj * D + lane * 4];
                    acc.x = fmaf(hv.x, aj, acc.x);
                    acc.y = fmaf(hv.y, aj, acc.y);
                    acc.z = fmaf(hv.z, aj, acc.z);
                    acc.w = fmaf(hv.w, aj, acc.w);
                }
            }
        }
    }

    float* o = out + (size_t)node * D + lane * 4;
    float4 r = *(float4*)o;
    r.x = selu_f(r.x + acc.x);
    r.y = selu_f(r.y + acc.y);
    r.z = selu_f(r.z + acc.z);
    r.w = selu_f(r.w + acc.w);
    *(float4*)o = r;
}

// ---------------- launch (fork edge-prep onto a side stream, overlap with GEMM) ----------------
extern "C" void kernel_launch(void* const* d_in, const int* in_sizes, int n_in,
                              void* d_out, int out_size) {
    const float* X      = (const float*)d_in[0];
    const int*   ei     = (const int*)  d_in[1];
    const int*   et     = (const int*)  d_in[2];
    const float* W      = (const float*)d_in[3];
    const float* W_r    = (const float*)d_in[4];
    const float* a      = (const float*)d_in[5];
    const float* W_res  = (const float*)d_in[6];
    const float* b_res  = (const float*)d_in[7];
    const float* rel    = (const float*)d_in[8];
    float* out = (float*)d_out;

    static cudaStream_t s2 = nullptr;
    static cudaEvent_t evF = nullptr, evJ = nullptr;
    if (s2 == nullptr) {
        cudaStreamCreateWithFlags(&s2, cudaStreamNonBlocking);
        cudaEventCreateWithFlags(&evF, cudaEventDisableTiming);
        cudaEventCreateWithFlags(&evJ, cudaEventDisableTiming);
    }

    k_prep<<<(N_NODES + 255) / 256, 256>>>(W, W_res, W_r, a, rel);

    cudaEventRecord(evF, 0);
    cudaStreamWaitEvent(s2, evF, 0);
    k_hist<<<(N_EDGES / 4 + 255) / 256, 256, 0, s2>>>(ei);
    k_alloc<<<(N_NODES + 1023) / 1024, 1024, 0, s2>>>();
    k_fill<<<(N_EDGES / 2 + 255) / 256, 256, 0, s2>>>(ei, et);
    cudaEventRecord(evJ, s2);

    dim3 ggrid((N_NODES + 127) / 128, 2);
    k_gemm_t<<<ggrid, 256>>>(X, b_res, a, out);

    cudaStreamWaitEvent(0, evJ, 0);
    k_agg<<<(N_NODES + 7) / 8, 256>>>(out);
}